// round 3
// baseline (speedup 1.0000x reference)
#include <cuda_runtime.h>
#include <math.h>
#include <stdint.h>

#define E_NN 50000
#define F_NN 25000
#define M_NN 100000
#define P_NN 75000
#define DD   128
#define HDD  384

// ---------------- scratch (device globals; no allocation allowed) ----------------
__device__ float g_h0[F_NN * DD];
__device__ float g_h1[F_NN * DD];
__device__ float g_haggr[F_NN * DD];
__device__ float g_ea[P_NN * DD];
__device__ float g_eattr[M_NN * DD];
__device__ float g_q[E_NN * HDD];
__device__ float g_k[F_NN * HDD];
__device__ float g_v[F_NN * HDD];
__device__ float g_ep[M_NN * HDD];
__device__ float g_alpha[M_NN * 3];
__device__ float g_amax[E_NN * 3];
__device__ float g_den[E_NN * 3];
__device__ float g_seg[E_NN * HDD];

// ---------------- small utility kernels ----------------
__global__ void fill_kernel(float* __restrict__ p, int n, float v) {
    int t = blockIdx.x * blockDim.x + threadIdx.x;
    if (t < n) p[t] = v;
}

__device__ __forceinline__ void atomicMaxFloat(float* addr, float val) {
    int* ia = (int*)addr;
    int old = *ia;
    while (val > __int_as_float(old)) {
        int assumed = old;
        old = atomicCAS(ia, assumed, __float_as_int(val));
        if (old == assumed) break;
    }
}

// h_aggr[f] += h_dE[e] * sgn  over cobdry edges. One warp per edge.
__global__ void scatter_aggr_kernel(const float* __restrict__ hE,
                                    const int* __restrict__ cob,
                                    float* __restrict__ haggr) {
    int t = blockIdx.x * blockDim.x + threadIdx.x;
    int e = t >> 5;
    if (e >= M_NN) return;
    int lane = t & 31;
    int ecol = cob[e * 3 + 0];
    int fcol = cob[e * 3 + 1];
    float s = (float)cob[e * 3 + 2];
    float4 v4 = ((const float4*)(hE + (size_t)ecol * DD))[lane];
    float* o = haggr + (size_t)fcol * DD + lane * 4;
    atomicAdd(o + 0, s * v4.x);
    atomicAdd(o + 1, s * v4.y);
    atomicAdd(o + 2, s * v4.z);
    atomicAdd(o + 3, s * v4.w);
}

// out[i][:] = src[idx[i*3+idxcol]][:]  (optionally * sign from signcol)
__global__ void gather_rows_kernel(const float* __restrict__ src,
                                   const int* __restrict__ idx,
                                   float* __restrict__ out,
                                   int E, int idxcol, int signcol) {
    int t = blockIdx.x * blockDim.x + threadIdx.x;
    int e = t >> 5;
    if (e >= E) return;
    int lane = t & 31;
    int r = idx[e * 3 + idxcol];
    float s = (signcol >= 0) ? (float)idx[e * 3 + signcol] : 1.0f;
    float4 v4 = ((const float4*)(src + (size_t)r * DD))[lane];
    v4.x *= s; v4.y *= s; v4.z *= s; v4.w *= s;
    ((float4*)(out + (size_t)e * DD))[lane] = v4;
}

// ---------------- 3xTF32 tensor-core GEMM ----------------
// C[M,N] = A[M,128] @ B[128,N] (+bias) (+=C)
// Each operand split into hi (tf32) + lo (tf32 of residual); three MMAs
// (hi*hi + hi*lo + lo*hi) recover near-fp32 accuracy.
// BM=BN=128, BK=16, 256 threads = 8 warps (2 m x 4 n), warp tile 64x32.

__device__ __forceinline__ uint32_t f2tf32(float x) {
    uint32_t r;
    asm("cvt.rna.tf32.f32 %0, %1;" : "=r"(r) : "f"(x));
    return r;
}

__device__ __forceinline__ void mma_tf32(float* d,
                                         uint32_t a0, uint32_t a1, uint32_t a2, uint32_t a3,
                                         uint32_t b0, uint32_t b1) {
    asm volatile(
        "mma.sync.aligned.m16n8k8.row.col.f32.tf32.tf32.f32 "
        "{%0,%1,%2,%3}, {%4,%5,%6,%7}, {%8,%9}, {%0,%1,%2,%3};\n"
        : "+f"(d[0]), "+f"(d[1]), "+f"(d[2]), "+f"(d[3])
        : "r"(a0), "r"(a1), "r"(a2), "r"(a3), "r"(b0), "r"(b1));
}

#define BM 128
#define BN 128
#define BK 16
#define SPAD 136   // row stride (u32) for [k][m] tiles; 136 % 32 == 8 -> conflict-free frags

__global__ __launch_bounds__(256) void gemm_k128(
    const float* __restrict__ A, const float* __restrict__ B,
    const float* __restrict__ bias, float* __restrict__ C,
    int M, int N, int accum)
{
    __shared__ uint32_t AsH[BK][SPAD];
    __shared__ uint32_t AsL[BK][SPAD];
    __shared__ uint32_t BsH[BK][SPAD];
    __shared__ uint32_t BsL[BK][SPAD];

    const int tid = threadIdx.x;
    const int lane = tid & 31;
    const int warp = tid >> 5;
    const int warp_m = warp & 1;   // m offset *64
    const int warp_n = warp >> 1;  // n offset *32
    const int row0 = blockIdx.y * BM;
    const int col0 = blockIdx.x * BN;

    const int grp = lane >> 2;     // 0..7
    const int qid = lane & 3;      // 0..3

    float acc[4][4][4];
#pragma unroll
    for (int i = 0; i < 4; i++)
#pragma unroll
        for (int j = 0; j < 4; j++)
#pragma unroll
            for (int r = 0; r < 4; r++) acc[i][j][r] = 0.f;

    // global->smem assignments (BK=16)
    const int a_kq = tid & 3;        // float4 idx along k: k = a_kq*4..+3
    const int a_r0 = tid >> 2;       // row 0..63, +64 second iter
    const int b_cq = tid & 31;       // float4 idx along n
    const int b_k0 = tid >> 5;       // k row 0..7, +8 second iter

    for (int k0 = 0; k0 < 128; k0 += BK) {
#pragma unroll
        for (int i = 0; i < 2; i++) {
            int r = a_r0 + i * 64;
            int gr = row0 + r;
            float4 va = make_float4(0.f, 0.f, 0.f, 0.f);
            if (gr < M) va = *(const float4*)(A + (size_t)gr * 128 + k0 + a_kq * 4);
            float vs[4] = {va.x, va.y, va.z, va.w};
#pragma unroll
            for (int t = 0; t < 4; t++) {
                uint32_t hi = f2tf32(vs[t]);
                float lo = vs[t] - __uint_as_float(hi);
                AsH[a_kq * 4 + t][r] = hi;
                AsL[a_kq * 4 + t][r] = f2tf32(lo);
            }
        }
#pragma unroll
        for (int i = 0; i < 2; i++) {
            int kk = b_k0 + i * 8;
            float4 vb = *(const float4*)(B + (size_t)(k0 + kk) * N + col0 + b_cq * 4);
            float vs[4] = {vb.x, vb.y, vb.z, vb.w};
#pragma unroll
            for (int t = 0; t < 4; t++) {
                uint32_t hi = f2tf32(vs[t]);
                float lo = vs[t] - __uint_as_float(hi);
                BsH[kk][b_cq * 4 + t] = hi;
                BsL[kk][b_cq * 4 + t] = f2tf32(lo);
            }
        }
        __syncthreads();

#pragma unroll
        for (int ks = 0; ks < BK; ks += 8) {
            uint32_t afH[4][4], afL[4][4];
            uint32_t bfH[4][2], bfL[4][2];
#pragma unroll
            for (int i = 0; i < 4; i++) {
                int mb = warp_m * 64 + i * 16;
                afH[i][0] = AsH[ks + qid][mb + grp];
                afH[i][1] = AsH[ks + qid][mb + grp + 8];
                afH[i][2] = AsH[ks + qid + 4][mb + grp];
                afH[i][3] = AsH[ks + qid + 4][mb + grp + 8];
                afL[i][0] = AsL[ks + qid][mb + grp];
                afL[i][1] = AsL[ks + qid][mb + grp + 8];
                afL[i][2] = AsL[ks + qid + 4][mb + grp];
                afL[i][3] = AsL[ks + qid + 4][mb + grp + 8];
            }
#pragma unroll
            for (int j = 0; j < 4; j++) {
                int nb = warp_n * 32 + j * 8;
                bfH[j][0] = BsH[ks + qid][nb + grp];
                bfH[j][1] = BsH[ks + qid + 4][nb + grp];
                bfL[j][0] = BsL[ks + qid][nb + grp];
                bfL[j][1] = BsL[ks + qid + 4][nb + grp];
            }
#pragma unroll
            for (int i = 0; i < 4; i++)
#pragma unroll
                for (int j = 0; j < 4; j++) {
                    mma_tf32(acc[i][j], afH[i][0], afH[i][1], afH[i][2], afH[i][3],
                             bfH[j][0], bfH[j][1]);
                    mma_tf32(acc[i][j], afH[i][0], afH[i][1], afH[i][2], afH[i][3],
                             bfL[j][0], bfL[j][1]);
                    mma_tf32(acc[i][j], afL[i][0], afL[i][1], afL[i][2], afL[i][3],
                             bfH[j][0], bfH[j][1]);
                }
        }
        __syncthreads();
    }

    // epilogue: d0,d1 at (row, col..col+1); d2,d3 at (row+8, col..col+1)
#pragma unroll
    for (int i = 0; i < 4; i++) {
        int row = row0 + warp_m * 64 + i * 16 + grp;
#pragma unroll
        for (int j = 0; j < 4; j++) {
            int col = col0 + warp_n * 32 + j * 8 + qid * 2;
#pragma unroll
            for (int half = 0; half < 2; half++) {
                int r = row + half * 8;
                if (r >= M) continue;
                float2 res;
                res.x = acc[i][j][half * 2 + 0];
                res.y = acc[i][j][half * 2 + 1];
                if (bias) {
                    res.x += bias[col + 0];
                    res.y += bias[col + 1];
                }
                float2* cp = (float2*)(C + (size_t)r * N + col);
                if (accum) {
                    float2 old = *cp;
                    res.x += old.x;
                    res.y += old.y;
                }
                *cp = res;
            }
        }
    }
}

// ---------------- attention kernels ----------------
__global__ void attn_alpha_kernel(const float* __restrict__ q,
                                  const float* __restrict__ k,
                                  const float* __restrict__ ep,
                                  const int* __restrict__ idx,
                                  int srcCol, int dstCol, int E,
                                  float* __restrict__ alpha,
                                  float* __restrict__ amax) {
    int e = blockIdx.x * 8 + (threadIdx.x >> 5);
    if (e >= E) return;
    int lane = threadIdx.x & 31;
    int src = idx[e * 3 + srcCol];
    int dst = idx[e * 3 + dstCol];
    const float4* qp = (const float4*)(q + (size_t)dst * HDD);
    const float4* kp = (const float4*)(k + (size_t)src * HDD);
    const float4* epp = (const float4*)(ep + (size_t)e * HDD);
#pragma unroll
    for (int h = 0; h < 3; h++) {
        float4 qv = qp[h * 32 + lane];
        float4 kv = kp[h * 32 + lane];
        float4 ev = epp[h * 32 + lane];
        float s = qv.x * (kv.x + ev.x) + qv.y * (kv.y + ev.y) +
                  qv.z * (kv.z + ev.z) + qv.w * (kv.w + ev.w);
#pragma unroll
        for (int o = 16; o > 0; o >>= 1) s += __shfl_xor_sync(0xffffffffu, s, o);
        if (lane == 0) {
            s *= 0.08838834764831845f;  // 1/sqrt(128)
            alpha[e * 3 + h] = s;
            atomicMaxFloat(&amax[dst * 3 + h], s);
        }
    }
}

__global__ void attn_expden_kernel(const int* __restrict__ idx, int dstCol, int E,
                                   float* __restrict__ alpha,
                                   const float* __restrict__ amax,
                                   float* __restrict__ den) {
    int t = blockIdx.x * blockDim.x + threadIdx.x;
    if (t >= E * 3) return;
    int e = t / 3, h = t - 3 * e;
    int dst = idx[e * 3 + dstCol];
    float ex = expf(alpha[t] - amax[dst * 3 + h]);
    alpha[t] = ex;
    atomicAdd(&den[dst * 3 + h], ex);
}

__global__ void attn_scatter_kernel(const float* __restrict__ v,
                                    const float* __restrict__ ep,
                                    const int* __restrict__ idx,
                                    int srcCol, int dstCol, int E,
                                    const float* __restrict__ alpha,
                                    const float* __restrict__ den,
                                    float* __restrict__ seg) {
    int e = blockIdx.x * 8 + (threadIdx.x >> 5);
    if (e >= E) return;
    int lane = threadIdx.x & 31;
    int src = idx[e * 3 + srcCol];
    int dst = idx[e * 3 + dstCol];
    const float4* vp = (const float4*)(v + (size_t)src * HDD);
    const float4* epp = (const float4*)(ep + (size_t)e * HDD);
    float* op = seg + (size_t)dst * HDD;
#pragma unroll
    for (int h = 0; h < 3; h++) {
        float w = alpha[e * 3 + h] / (den[dst * 3 + h] + 1e-16f);
        float4 vv = vp[h * 32 + lane];
        float4 ev = epp[h * 32 + lane];
        int c = h * 128 + lane * 4;
        atomicAdd(op + c + 0, w * (vv.x + ev.x));
        atomicAdd(op + c + 1, w * (vv.y + ev.y));
        atomicAdd(op + c + 2, w * (vv.z + ev.z));
        atomicAdd(op + c + 3, w * (vv.w + ev.w));
    }
}

__global__ void combine_kernel(const float* __restrict__ seg,
                               const float* __restrict__ hin,
                               float* __restrict__ out, int n) {
    int t = blockIdx.x * blockDim.x + threadIdx.x;
    if (t >= n * DD) return;
    int node = t >> 7, d = t & 127;
    const float* s = seg + (size_t)node * HDD;
    float m = (s[d] + s[128 + d] + s[256 + d]) * (1.0f / 3.0f);
    out[t] = hin ? (m + hin[t]) : m;
}

// ---------------- host orchestration ----------------
static inline int cdiv(int a, int b) { return (a + b - 1) / b; }

extern "C" void kernel_launch(void* const* d_in, const int* in_sizes, int n_in,
                              void* d_out, int out_size) {
    const float* h_dE = (const float*)d_in[0];
    const float* h_dF = (const float*)d_in[1];
    const int* cob = (const int*)d_in[2];
    const int* nn = (const int*)d_in[3];
    const float* aggr_W = (const float*)d_in[4];
    const float* aggr_b = (const float*)d_in[5];
    const float* ctr_W = (const float*)d_in[6];
    const float* ctr_b = (const float*)d_in[7];
    const float* f_Wq = (const float*)d_in[8];
    const float* f_bq = (const float*)d_in[9];
    const float* f_Wk = (const float*)d_in[10];
    const float* f_bk = (const float*)d_in[11];
    const float* f_Wv = (const float*)d_in[12];
    const float* f_bv = (const float*)d_in[13];
    const float* f_We = (const float*)d_in[14];
    const float* f_Ws = (const float*)d_in[15];
    const float* f_bs = (const float*)d_in[16];
    const float* e_Wq = (const float*)d_in[17];
    const float* e_bq = (const float*)d_in[18];
    const float* e_Wk = (const float*)d_in[19];
    const float* e_bk = (const float*)d_in[20];
    const float* e_Wv = (const float*)d_in[21];
    const float* e_bv = (const float*)d_in[22];
    const float* e_We = (const float*)d_in[23];
    const float* e_Ws = (const float*)d_in[24];
    const float* e_bs = (const float*)d_in[25];
    float* out = (float*)d_out;

    float *h0, *h1, *haggr, *ea, *eattr, *q, *k, *v, *ep, *alpha, *amax, *den, *seg;
    cudaGetSymbolAddress((void**)&h0, g_h0);
    cudaGetSymbolAddress((void**)&h1, g_h1);
    cudaGetSymbolAddress((void**)&haggr, g_haggr);
    cudaGetSymbolAddress((void**)&ea, g_ea);
    cudaGetSymbolAddress((void**)&eattr, g_eattr);
    cudaGetSymbolAddress((void**)&q, g_q);
    cudaGetSymbolAddress((void**)&k, g_k);
    cudaGetSymbolAddress((void**)&v, g_v);
    cudaGetSymbolAddress((void**)&ep, g_ep);
    cudaGetSymbolAddress((void**)&alpha, g_alpha);
    cudaGetSymbolAddress((void**)&amax, g_amax);
    cudaGetSymbolAddress((void**)&den, g_den);
    cudaGetSymbolAddress((void**)&seg, g_seg);

    const float NEG_INF = -INFINITY;

    // 1) h_aggr = segment_sum(h_dE[e]*sgn over f)
    fill_kernel<<<cdiv(F_NN * DD, 256), 256>>>(haggr, F_NN * DD, 0.f);
    scatter_aggr_kernel<<<cdiv(M_NN * 32, 256), 256>>>(h_dE, cob, haggr);

    // 2) h = h_aggr@aggr_W + aggr_b + h_dF@ctr_W + ctr_b
    {
        dim3 g(1, cdiv(F_NN, 128));
        gemm_k128<<<g, 256>>>(haggr, aggr_W, aggr_b, h0, F_NN, 128, 0);
        gemm_k128<<<g, 256>>>(h_dF, ctr_W, ctr_b, h0, F_NN, 128, 1);
    }

    // 3) ea = h_dE[nn[:,2]]  (constant across layers)
    gather_rows_kernel<<<cdiv(P_NN * 32, 256), 256>>>(h_dE, nn, ea, P_NN, 2, -1);

    float* hcur = h0;
    float* hnext = h1;
    for (int l = 0; l < 3; l++) {
        const float* Wq = f_Wq + (size_t)l * 128 * 384;
        const float* bq = f_bq + (size_t)l * 384;
        const float* Wk = f_Wk + (size_t)l * 128 * 384;
        const float* bk = f_bk + (size_t)l * 384;
        const float* Wv = f_Wv + (size_t)l * 128 * 384;
        const float* bv = f_bv + (size_t)l * 384;
        const float* We = f_We + (size_t)l * 128 * 384;
        const float* Ws = f_Ws + (size_t)l * 128 * 128;
        const float* bs = f_bs + (size_t)l * 128;

        dim3 g3(3, cdiv(F_NN, 128));
        gemm_k128<<<g3, 256>>>(hcur, Wq, bq, q, F_NN, 384, 0);
        gemm_k128<<<g3, 256>>>(hcur, Wk, bk, k, F_NN, 384, 0);
        gemm_k128<<<g3, 256>>>(hcur, Wv, bv, v, F_NN, 384, 0);
        dim3 ge(3, cdiv(P_NN, 128));
        gemm_k128<<<ge, 256>>>(ea, We, nullptr, ep, P_NN, 384, 0);

        fill_kernel<<<cdiv(F_NN * 3, 256), 256>>>(amax, F_NN * 3, NEG_INF);
        fill_kernel<<<cdiv(F_NN * 3, 256), 256>>>(den, F_NN * 3, 0.f);
        fill_kernel<<<cdiv(F_NN * HDD, 256), 256>>>(seg, F_NN * HDD, 0.f);

        attn_alpha_kernel<<<cdiv(P_NN, 8), 256>>>(q, k, ep, nn, 0, 1, P_NN, alpha, amax);
        attn_expden_kernel<<<cdiv(P_NN * 3, 256), 256>>>(nn, 1, P_NN, alpha, amax, den);
        attn_scatter_kernel<<<cdiv(P_NN, 8), 256>>>(v, ep, nn, 0, 1, P_NN, alpha, den, seg);

        combine_kernel<<<cdiv(F_NN * DD, 256), 256>>>(seg, hcur, hnext, F_NN);
        dim3 g1(1, cdiv(F_NN, 128));
        gemm_k128<<<g1, 256>>>(hcur, Ws, bs, hnext, F_NN, 128, 1);

        float* tmp = hcur; hcur = hnext; hnext = tmp;
    }

    // final cross attention: F -> E over cobdry edges (src=f_col(1), dst=e_col(0))
    gather_rows_kernel<<<cdiv(M_NN * 32, 256), 256>>>(hcur, cob, eattr, M_NN, 1, 2);

    {
        dim3 gq(3, cdiv(E_NN, 128));
        gemm_k128<<<gq, 256>>>(h_dE, e_Wq, e_bq, q, E_NN, 384, 0);
        dim3 gk(3, cdiv(F_NN, 128));
        gemm_k128<<<gk, 256>>>(hcur, e_Wk, e_bk, k, F_NN, 384, 0);
        gemm_k128<<<gk, 256>>>(hcur, e_Wv, e_bv, v, F_NN, 384, 0);
        dim3 ge(3, cdiv(M_NN, 128));
        gemm_k128<<<ge, 256>>>(eattr, e_We, nullptr, ep, M_NN, 384, 0);
    }

    fill_kernel<<<cdiv(E_NN * 3, 256), 256>>>(amax, E_NN * 3, NEG_INF);
    fill_kernel<<<cdiv(E_NN * 3, 256), 256>>>(den, E_NN * 3, 0.f);
    fill_kernel<<<cdiv(E_NN * HDD, 256), 256>>>(seg, E_NN * HDD, 0.f);

    attn_alpha_kernel<<<cdiv(M_NN, 8), 256>>>(q, k, ep, cob, 1, 0, M_NN, alpha, amax);
    attn_expden_kernel<<<cdiv(M_NN * 3, 256), 256>>>(cob, 0, M_NN, alpha, amax, den);
    attn_scatter_kernel<<<cdiv(M_NN, 8), 256>>>(v, ep, cob, 1, 0, M_NN, alpha, den, seg);

    combine_kernel<<<cdiv(E_NN * DD, 256), 256>>>(seg, nullptr, out, E_NN);
    {
        dim3 g1(1, cdiv(E_NN, 128));
        gemm_k128<<<g1, 256>>>(h_dE, e_Ws, e_bs, out, E_NN, 128, 1);
    }
}

// round 4
// speedup vs baseline: 1.0598x; 1.0598x over previous
#include <cuda_runtime.h>
#include <math.h>
#include <stdint.h>

#define E_NN 50000
#define F_NN 25000
#define M_NN 100000
#define P_NN 75000
#define DD   128
#define HDD  384

// ---------------- scratch (device globals; no allocation allowed) ----------------
__device__ float g_h0[F_NN * DD];
__device__ float g_h1[F_NN * DD];
__device__ float g_haggr[F_NN * DD];   // init aggr; later reused as Ws output (F)
__device__ float g_wsE[E_NN * DD];     // Ws output (E, final layer)
__device__ float g_q[E_NN * HDD];
__device__ float g_k[F_NN * HDD];
__device__ float g_v[F_NN * HDD];
__device__ float g_ep[M_NN * HDD];
__device__ float g_alpha[M_NN * 3];
__device__ float g_amax[E_NN * 3];
__device__ float g_den[E_NN * 3];
__device__ float g_seg[E_NN * HDD];

// ---------------- small utility kernels ----------------
__global__ void fill_kernel(float* __restrict__ p, int n, float v) {
    int t = blockIdx.x * blockDim.x + threadIdx.x;
    if (t < n) p[t] = v;
}

__device__ __forceinline__ void atomicMaxFloat(float* addr, float val) {
    int* ia = (int*)addr;
    int old = *ia;
    while (val > __int_as_float(old)) {
        int assumed = old;
        old = atomicCAS(ia, assumed, __float_as_int(val));
        if (old == assumed) break;
    }
}

// h_aggr[f] += h_dE[e] * sgn  over cobdry edges. One warp per edge.
__global__ void scatter_aggr_kernel(const float* __restrict__ hE,
                                    const int* __restrict__ cob,
                                    float* __restrict__ haggr) {
    int t = blockIdx.x * blockDim.x + threadIdx.x;
    int e = t >> 5;
    if (e >= M_NN) return;
    int lane = t & 31;
    int ecol = cob[e * 3 + 0];
    int fcol = cob[e * 3 + 1];
    float s = (float)cob[e * 3 + 2];
    float4 v4 = ((const float4*)(hE + (size_t)ecol * DD))[lane];
    float* o = haggr + (size_t)fcol * DD + lane * 4;
    atomicAdd(o + 0, s * v4.x);
    atomicAdd(o + 1, s * v4.y);
    atomicAdd(o + 2, s * v4.z);
    atomicAdd(o + 3, s * v4.w);
}

// ---------------- 3xTF32 tensor-core GEMM (pipelined, multi-output) ----------------
// C[M,N] = A[M,128] @ B[128,N] (+bias) (+=C) per "segment" selected by blockIdx.x.
// A rows optionally gathered: A[aIdx[r*3+aCol]] * (float)aIdx[r*3+aSgnCol].
// cp.async double-buffered staging hides global latency; hi/lo TF32 split gives
// near-fp32 accuracy with 3 MMAs.

__device__ __forceinline__ uint32_t f2tf32(float x) {
    uint32_t r;
    asm("cvt.rna.tf32.f32 %0, %1;" : "=r"(r) : "f"(x));
    return r;
}

__device__ __forceinline__ void mma_tf32(float* d,
                                         uint32_t a0, uint32_t a1, uint32_t a2, uint32_t a3,
                                         uint32_t b0, uint32_t b1) {
    asm volatile(
        "mma.sync.aligned.m16n8k8.row.col.f32.tf32.tf32.f32 "
        "{%0,%1,%2,%3}, {%4,%5,%6,%7}, {%8,%9}, {%0,%1,%2,%3};\n"
        : "+f"(d[0]), "+f"(d[1]), "+f"(d[2]), "+f"(d[3])
        : "r"(a0), "r"(a1), "r"(a2), "r"(a3), "r"(b0), "r"(b1));
}

__device__ __forceinline__ void cp16(void* smemDst, const void* gsrc) {
    uint32_t s = (uint32_t)__cvta_generic_to_shared(smemDst);
    asm volatile("cp.async.ca.shared.global [%0], [%1], 16;\n" :: "r"(s), "l"(gsrc));
}
#define CP_COMMIT() asm volatile("cp.async.commit_group;\n")
#define CP_WAIT(n)  asm volatile("cp.async.wait_group %0;\n" :: "n"(n))

#define BM 128
#define BN 128
#define BK 16
#define SPAD 136   // row stride (u32); 136 % 32 == 8 -> conflict-free frag loads
#define TILE_U32 (BK * SPAD)                    // 2176
#define SMEM_TILES_BYTES (4 * TILE_U32 * 4)     // 34816
#define SMEM_STG_BYTES   (2 * 2 * 256 * 16 * 2) // stgA + stgB = 32768
#define GEMM_SMEM (SMEM_TILES_BYTES + SMEM_STG_BYTES)  // 67584

struct GSegs {
    const float* B[4];
    const float* bias[4];
    float* C[4];
    int N[4];
    int acc[4];
    int start[4];
    int nseg;
};

__global__ __launch_bounds__(256, 2) void gemm_multi(
    const float* __restrict__ A, int M,
    const int* __restrict__ aIdx, int aCol, int aSgnCol,
    GSegs segs)
{
    extern __shared__ char smem[];
    uint32_t (*AsH)[SPAD] = (uint32_t(*)[SPAD])(smem);
    uint32_t (*AsL)[SPAD] = (uint32_t(*)[SPAD])(smem + TILE_U32 * 4);
    uint32_t (*BsH)[SPAD] = (uint32_t(*)[SPAD])(smem + TILE_U32 * 8);
    uint32_t (*BsL)[SPAD] = (uint32_t(*)[SPAD])(smem + TILE_U32 * 12);
    float4* stgA = (float4*)(smem + SMEM_TILES_BYTES);           // [2][2][256]
    float4* stgB = (float4*)(smem + SMEM_TILES_BYTES + 16384);   // [2][2][256]

    const int tid = threadIdx.x;
    const int lane = tid & 31;
    const int warp = tid >> 5;
    const int warp_m = warp & 1;
    const int warp_n = warp >> 1;
    const int row0 = blockIdx.y * BM;

    // segment resolution
    int s = 0;
#pragma unroll
    for (int t = 1; t < 4; t++)
        if (t < segs.nseg && (int)blockIdx.x >= segs.start[t]) s = t;
    const float* Bp = segs.B[s];
    const float* bias = segs.bias[s];
    float* C = segs.C[s];
    const int N = segs.N[s];
    const int accum = segs.acc[s];
    const int col0 = (blockIdx.x - segs.start[s]) * BN;

    const int grp = lane >> 2;
    const int qid = lane & 3;

    // loader assignments
    const int a_kq = tid & 3;        // k float4 within BK
    const int a_r0 = tid >> 2;       // row 0..63 (+64 second)
    const int b_cq = tid & 31;       // n float4
    const int b_k0 = tid >> 5;       // k row 0..7 (+8 second)

    // resolve A rows (gather + sign; OOB rows -> row 0 with sign 0)
    int ar[2];
    float asgn[2];
#pragma unroll
    for (int i = 0; i < 2; i++) {
        int gr = row0 + a_r0 + i * 64;
        if (gr < M) {
            if (aIdx) {
                ar[i] = aIdx[(size_t)gr * 3 + aCol];
                asgn[i] = (aSgnCol >= 0) ? (float)aIdx[(size_t)gr * 3 + aSgnCol] : 1.0f;
            } else {
                ar[i] = gr;
                asgn[i] = 1.0f;
            }
        } else {
            ar[i] = 0;
            asgn[i] = 0.0f;
        }
    }

    float acc[4][4][4];
#pragma unroll
    for (int i = 0; i < 4; i++)
#pragma unroll
        for (int j = 0; j < 4; j++)
#pragma unroll
            for (int r = 0; r < 4; r++) acc[i][j][r] = 0.f;

    // stage k0 chunk into staging buffers (each thread stages exactly what it converts)
    auto stage = [&](int st, int k0) {
#pragma unroll
        for (int i = 0; i < 2; i++)
            cp16(&stgA[(st * 2 + i) * 256 + tid],
                 A + (size_t)ar[i] * 128 + k0 + a_kq * 4);
#pragma unroll
        for (int i = 0; i < 2; i++)
            cp16(&stgB[(st * 2 + i) * 256 + tid],
                 Bp + (size_t)(k0 + b_k0 + i * 8) * N + col0 + b_cq * 4);
    };

    int st = 0;
    stage(0, 0);
    CP_COMMIT();

    for (int k0 = 0; k0 < 128; k0 += BK) {
        if (k0 + BK < 128) {
            stage(st ^ 1, k0 + BK);
            CP_COMMIT();
            CP_WAIT(1);
        } else {
            CP_WAIT(0);
        }

        // convert own staged data into hi/lo tiles
#pragma unroll
        for (int i = 0; i < 2; i++) {
            float4 va = stgA[(st * 2 + i) * 256 + tid];
            float vs[4] = {va.x * asgn[i], va.y * asgn[i], va.z * asgn[i], va.w * asgn[i]};
            int r = a_r0 + i * 64;
#pragma unroll
            for (int t = 0; t < 4; t++) {
                uint32_t hi = f2tf32(vs[t]);
                AsH[a_kq * 4 + t][r] = hi;
                AsL[a_kq * 4 + t][r] = f2tf32(vs[t] - __uint_as_float(hi));
            }
        }
#pragma unroll
        for (int i = 0; i < 2; i++) {
            float4 vb = stgB[(st * 2 + i) * 256 + tid];
            float vs[4] = {vb.x, vb.y, vb.z, vb.w};
            int kk = b_k0 + i * 8;
#pragma unroll
            for (int t = 0; t < 4; t++) {
                uint32_t hi = f2tf32(vs[t]);
                BsH[kk][b_cq * 4 + t] = hi;
                BsL[kk][b_cq * 4 + t] = f2tf32(vs[t] - __uint_as_float(hi));
            }
        }
        __syncthreads();

#pragma unroll
        for (int ks = 0; ks < BK; ks += 8) {
            uint32_t afH[4][4], afL[4][4];
            uint32_t bfH[4][2], bfL[4][2];
#pragma unroll
            for (int i = 0; i < 4; i++) {
                int mb = warp_m * 64 + i * 16;
                afH[i][0] = AsH[ks + qid][mb + grp];
                afH[i][1] = AsH[ks + qid][mb + grp + 8];
                afH[i][2] = AsH[ks + qid + 4][mb + grp];
                afH[i][3] = AsH[ks + qid + 4][mb + grp + 8];
                afL[i][0] = AsL[ks + qid][mb + grp];
                afL[i][1] = AsL[ks + qid][mb + grp + 8];
                afL[i][2] = AsL[ks + qid + 4][mb + grp];
                afL[i][3] = AsL[ks + qid + 4][mb + grp + 8];
            }
#pragma unroll
            for (int j = 0; j < 4; j++) {
                int nb = warp_n * 32 + j * 8;
                bfH[j][0] = BsH[ks + qid][nb + grp];
                bfH[j][1] = BsH[ks + qid + 4][nb + grp];
                bfL[j][0] = BsL[ks + qid][nb + grp];
                bfL[j][1] = BsL[ks + qid + 4][nb + grp];
            }
#pragma unroll
            for (int i = 0; i < 4; i++)
#pragma unroll
                for (int j = 0; j < 4; j++) {
                    mma_tf32(acc[i][j], afH[i][0], afH[i][1], afH[i][2], afH[i][3],
                             bfH[j][0], bfH[j][1]);
                    mma_tf32(acc[i][j], afH[i][0], afH[i][1], afH[i][2], afH[i][3],
                             bfL[j][0], bfL[j][1]);
                    mma_tf32(acc[i][j], afL[i][0], afL[i][1], afL[i][2], afL[i][3],
                             bfH[j][0], bfH[j][1]);
                }
        }
        __syncthreads();
        st ^= 1;
    }

    // epilogue
#pragma unroll
    for (int i = 0; i < 4; i++) {
        int row = row0 + warp_m * 64 + i * 16 + grp;
#pragma unroll
        for (int j = 0; j < 4; j++) {
            int col = col0 + warp_n * 32 + j * 8 + qid * 2;
#pragma unroll
            for (int half = 0; half < 2; half++) {
                int r = row + half * 8;
                if (r >= M) continue;
                float2 res;
                res.x = acc[i][j][half * 2 + 0];
                res.y = acc[i][j][half * 2 + 1];
                if (bias) {
                    res.x += bias[col + 0];
                    res.y += bias[col + 1];
                }
                float2* cp = (float2*)(C + (size_t)r * N + col);
                if (accum) {
                    float2 old = *cp;
                    res.x += old.x;
                    res.y += old.y;
                }
                *cp = res;
            }
        }
    }
}

// ---------------- attention kernels ----------------
__global__ void attn_alpha_kernel(const float* __restrict__ q,
                                  const float* __restrict__ k,
                                  const float* __restrict__ ep,
                                  const int* __restrict__ idx,
                                  int srcCol, int dstCol, int E,
                                  float* __restrict__ alpha,
                                  float* __restrict__ amax) {
    int e = blockIdx.x * 8 + (threadIdx.x >> 5);
    if (e >= E) return;
    int lane = threadIdx.x & 31;
    int src = idx[e * 3 + srcCol];
    int dst = idx[e * 3 + dstCol];
    const float4* qp = (const float4*)(q + (size_t)dst * HDD);
    const float4* kp = (const float4*)(k + (size_t)src * HDD);
    const float4* epp = (const float4*)(ep + (size_t)e * HDD);
#pragma unroll
    for (int h = 0; h < 3; h++) {
        float4 qv = qp[h * 32 + lane];
        float4 kv = kp[h * 32 + lane];
        float4 ev = epp[h * 32 + lane];
        float s = qv.x * (kv.x + ev.x) + qv.y * (kv.y + ev.y) +
                  qv.z * (kv.z + ev.z) + qv.w * (kv.w + ev.w);
#pragma unroll
        for (int o = 16; o > 0; o >>= 1) s += __shfl_xor_sync(0xffffffffu, s, o);
        if (lane == 0) {
            s *= 0.08838834764831845f;  // 1/sqrt(128)
            alpha[e * 3 + h] = s;
            atomicMaxFloat(&amax[dst * 3 + h], s);
        }
    }
}

__global__ void attn_expden_kernel(const int* __restrict__ idx, int dstCol, int E,
                                   float* __restrict__ alpha,
                                   const float* __restrict__ amax,
                                   float* __restrict__ den) {
    int t = blockIdx.x * blockDim.x + threadIdx.x;
    if (t >= E * 3) return;
    int e = t / 3, h = t - 3 * e;
    int dst = idx[e * 3 + dstCol];
    float ex = expf(alpha[t] - amax[dst * 3 + h]);
    alpha[t] = ex;
    atomicAdd(&den[dst * 3 + h], ex);
}

__global__ void attn_scatter_kernel(const float* __restrict__ v,
                                    const float* __restrict__ ep,
                                    const int* __restrict__ idx,
                                    int srcCol, int dstCol, int E,
                                    const float* __restrict__ alpha,
                                    const float* __restrict__ den,
                                    float* __restrict__ seg) {
    int e = blockIdx.x * 8 + (threadIdx.x >> 5);
    if (e >= E) return;
    int lane = threadIdx.x & 31;
    int src = idx[e * 3 + srcCol];
    int dst = idx[e * 3 + dstCol];
    const float4* vp = (const float4*)(v + (size_t)src * HDD);
    const float4* epp = (const float4*)(ep + (size_t)e * HDD);
    float* op = seg + (size_t)dst * HDD;
#pragma unroll
    for (int h = 0; h < 3; h++) {
        float w = alpha[e * 3 + h] / (den[dst * 3 + h] + 1e-16f);
        float4 vv = vp[h * 32 + lane];
        float4 ev = epp[h * 32 + lane];
        int c = h * 128 + lane * 4;
        atomicAdd(op + c + 0, w * (vv.x + ev.x));
        atomicAdd(op + c + 1, w * (vv.y + ev.y));
        atomicAdd(op + c + 2, w * (vv.z + ev.z));
        atomicAdd(op + c + 3, w * (vv.w + ev.w));
    }
}

// out = mean over heads (+ residual hin) (+ ws projection)
__global__ void combine_kernel(const float* __restrict__ seg,
                               const float* __restrict__ hin,
                               const float* __restrict__ ws,
                               float* __restrict__ out, int n) {
    int t = blockIdx.x * blockDim.x + threadIdx.x;
    if (t >= n * DD) return;
    int node = t >> 7, d = t & 127;
    const float* s = seg + (size_t)node * HDD;
    float m = (s[d] + s[128 + d] + s[256 + d]) * (1.0f / 3.0f);
    if (hin) m += hin[t];
    if (ws) m += ws[t];
    out[t] = m;
}

// ---------------- host orchestration ----------------
static inline int cdiv(int a, int b) { return (a + b - 1) / b; }

static GSegs mk1(const float* B, const float* bias, float* C, int N, int acc) {
    GSegs s = {};
    s.B[0] = B; s.bias[0] = bias; s.C[0] = C; s.N[0] = N; s.acc[0] = acc;
    s.start[0] = 0; s.nseg = 1;
    return s;
}

extern "C" void kernel_launch(void* const* d_in, const int* in_sizes, int n_in,
                              void* d_out, int out_size) {
    const float* h_dE = (const float*)d_in[0];
    const float* h_dF = (const float*)d_in[1];
    const int* cob = (const int*)d_in[2];
    const int* nn = (const int*)d_in[3];
    const float* aggr_W = (const float*)d_in[4];
    const float* aggr_b = (const float*)d_in[5];
    const float* ctr_W = (const float*)d_in[6];
    const float* ctr_b = (const float*)d_in[7];
    const float* f_Wq = (const float*)d_in[8];
    const float* f_bq = (const float*)d_in[9];
    const float* f_Wk = (const float*)d_in[10];
    const float* f_bk = (const float*)d_in[11];
    const float* f_Wv = (const float*)d_in[12];
    const float* f_bv = (const float*)d_in[13];
    const float* f_We = (const float*)d_in[14];
    const float* f_Ws = (const float*)d_in[15];
    const float* f_bs = (const float*)d_in[16];
    const float* e_Wq = (const float*)d_in[17];
    const float* e_bq = (const float*)d_in[18];
    const float* e_Wk = (const float*)d_in[19];
    const float* e_bk = (const float*)d_in[20];
    const float* e_Wv = (const float*)d_in[21];
    const float* e_bv = (const float*)d_in[22];
    const float* e_We = (const float*)d_in[23];
    const float* e_Ws = (const float*)d_in[24];
    const float* e_bs = (const float*)d_in[25];
    float* out = (float*)d_out;

    cudaFuncSetAttribute(gemm_multi, cudaFuncAttributeMaxDynamicSharedMemorySize, GEMM_SMEM);

    float *h0, *h1, *haggr, *wsE, *q, *k, *v, *ep, *alpha, *amax, *den, *seg;
    cudaGetSymbolAddress((void**)&h0, g_h0);
    cudaGetSymbolAddress((void**)&h1, g_h1);
    cudaGetSymbolAddress((void**)&haggr, g_haggr);
    cudaGetSymbolAddress((void**)&wsE, g_wsE);
    cudaGetSymbolAddress((void**)&q, g_q);
    cudaGetSymbolAddress((void**)&k, g_k);
    cudaGetSymbolAddress((void**)&v, g_v);
    cudaGetSymbolAddress((void**)&ep, g_ep);
    cudaGetSymbolAddress((void**)&alpha, g_alpha);
    cudaGetSymbolAddress((void**)&amax, g_amax);
    cudaGetSymbolAddress((void**)&den, g_den);
    cudaGetSymbolAddress((void**)&seg, g_seg);

    const float NEG_INF = -INFINITY;
    const int FY = cdiv(F_NN, 128);   // 196
    const int EY = cdiv(E_NN, 128);   // 391
    const int PY = cdiv(P_NN, 128);   // 586
    const int MY = cdiv(M_NN, 128);   // 782

    // 1) h_aggr = segment_sum(h_dE[e]*sgn over f)
    fill_kernel<<<cdiv(F_NN * DD, 256), 256>>>(haggr, F_NN * DD, 0.f);
    scatter_aggr_kernel<<<cdiv(M_NN * 32, 256), 256>>>(h_dE, cob, haggr);

    // 2) h = h_aggr@aggr_W + aggr_b + h_dF@ctr_W + ctr_b
    {
        GSegs s1 = mk1(aggr_W, aggr_b, h0, 128, 0);
        gemm_multi<<<dim3(1, FY), 256, GEMM_SMEM>>>(haggr, F_NN, nullptr, 0, -1, s1);
        GSegs s2 = mk1(ctr_W, ctr_b, h0, 128, 1);
        gemm_multi<<<dim3(1, FY), 256, GEMM_SMEM>>>(h_dF, F_NN, nullptr, 0, -1, s2);
    }

    float* hcur = h0;
    float* hnext = h1;
    for (int l = 0; l < 3; l++) {
        const float* Wq = f_Wq + (size_t)l * 128 * 384;
        const float* bq = f_bq + (size_t)l * 384;
        const float* Wk = f_Wk + (size_t)l * 128 * 384;
        const float* bk = f_bk + (size_t)l * 384;
        const float* Wv = f_Wv + (size_t)l * 128 * 384;
        const float* bv = f_bv + (size_t)l * 384;
        const float* We = f_We + (size_t)l * 128 * 384;
        const float* Ws = f_Ws + (size_t)l * 128 * 128;
        const float* bs = f_bs + (size_t)l * 128;

        // fused q,k,v,Ws GEMM over hcur
        GSegs sq = {};
        sq.B[0] = Wq; sq.bias[0] = bq; sq.C[0] = q;     sq.N[0] = 384; sq.acc[0] = 0; sq.start[0] = 0;
        sq.B[1] = Wk; sq.bias[1] = bk; sq.C[1] = k;     sq.N[1] = 384; sq.acc[1] = 0; sq.start[1] = 3;
        sq.B[2] = Wv; sq.bias[2] = bv; sq.C[2] = v;     sq.N[2] = 384; sq.acc[2] = 0; sq.start[2] = 6;
        sq.B[3] = Ws; sq.bias[3] = bs; sq.C[3] = haggr; sq.N[3] = 128; sq.acc[3] = 0; sq.start[3] = 9;
        sq.nseg = 4;
        gemm_multi<<<dim3(10, FY), 256, GEMM_SMEM>>>(hcur, F_NN, nullptr, 0, -1, sq);

        // ep = h_dE[nn[:,2]] @ We  (gather fused into A load)
        GSegs se = mk1(We, nullptr, ep, 384, 0);
        gemm_multi<<<dim3(3, PY), 256, GEMM_SMEM>>>(h_dE, P_NN, nn, 2, -1, se);

        fill_kernel<<<cdiv(F_NN * 3, 256), 256>>>(amax, F_NN * 3, NEG_INF);
        fill_kernel<<<cdiv(F_NN * 3, 256), 256>>>(den, F_NN * 3, 0.f);
        fill_kernel<<<cdiv(F_NN * HDD, 256), 256>>>(seg, F_NN * HDD, 0.f);

        attn_alpha_kernel<<<cdiv(P_NN, 8), 256>>>(q, k, ep, nn, 0, 1, P_NN, alpha, amax);
        attn_expden_kernel<<<cdiv(P_NN * 3, 256), 256>>>(nn, 1, P_NN, alpha, amax, den);
        attn_scatter_kernel<<<cdiv(P_NN, 8), 256>>>(v, ep, nn, 0, 1, P_NN, alpha, den, seg);

        combine_kernel<<<cdiv(F_NN * DD, 256), 256>>>(seg, hcur, haggr, hnext, F_NN);

        float* tmp = hcur; hcur = hnext; hnext = tmp;
    }

    // final cross attention: F -> E over cobdry edges (src=f_col(1), dst=e_col(0))
    {
        // q (E rows) + Ws (E rows) fused
        GSegs sq = {};
        sq.B[0] = e_Wq; sq.bias[0] = e_bq; sq.C[0] = q;   sq.N[0] = 384; sq.acc[0] = 0; sq.start[0] = 0;
        sq.B[1] = e_Ws; sq.bias[1] = e_bs; sq.C[1] = wsE; sq.N[1] = 128; sq.acc[1] = 0; sq.start[1] = 3;
        sq.nseg = 2;
        gemm_multi<<<dim3(4, EY), 256, GEMM_SMEM>>>(h_dE, E_NN, nullptr, 0, -1, sq);

        // k + v (F rows) fused
        GSegs skv = {};
        skv.B[0] = e_Wk; skv.bias[0] = e_bk; skv.C[0] = k; skv.N[0] = 384; skv.acc[0] = 0; skv.start[0] = 0;
        skv.B[1] = e_Wv; skv.bias[1] = e_bv; skv.C[1] = v; skv.N[1] = 384; skv.acc[1] = 0; skv.start[1] = 3;
        skv.nseg = 2;
        gemm_multi<<<dim3(6, FY), 256, GEMM_SMEM>>>(hcur, F_NN, nullptr, 0, -1, skv);

        // ep = (hcur[cob[:,1]] * sgn) @ e_We  (gather+sign fused)
        GSegs se = mk1(e_We, nullptr, ep, 384, 0);
        gemm_multi<<<dim3(3, MY), 256, GEMM_SMEM>>>(hcur, M_NN, cob, 1, 2, se);
    }

    fill_kernel<<<cdiv(E_NN * 3, 256), 256>>>(amax, E_NN * 3, NEG_INF);
    fill_kernel<<<cdiv(E_NN * 3, 256), 256>>>(den, E_NN * 3, 0.f);
    fill_kernel<<<cdiv(E_NN * HDD, 256), 256>>>(seg, E_NN * HDD, 0.f);

    attn_alpha_kernel<<<cdiv(M_NN, 8), 256>>>(q, k, ep, cob, 1, 0, M_NN, alpha, amax);
    attn_expden_kernel<<<cdiv(M_NN * 3, 256), 256>>>(cob, 0, M_NN, alpha, amax, den);
    attn_scatter_kernel<<<cdiv(M_NN, 8), 256>>>(v, ep, cob, 1, 0, M_NN, alpha, den, seg);

    combine_kernel<<<cdiv(E_NN * DD, 256), 256>>>(seg, nullptr, wsE, out, E_NN);
}

// round 5
// speedup vs baseline: 1.5942x; 1.5042x over previous
#include <cuda_runtime.h>
#include <cuda_bf16.h>
#include <math.h>
#include <stdint.h>

#define E_NN 50000
#define F_NN 25000
#define M_NN 100000
#define P_NN 75000
#define DD   128
#define HDD  384

// ---------------- scratch (device globals; no allocation allowed) ----------------
__device__ float g_h0[F_NN * DD];
__device__ float g_h1[F_NN * DD];
__device__ float g_haggr[F_NN * DD];   // init aggr; later reused as Ws output (F)
__device__ float g_wsE[E_NN * DD];     // Ws output (E, final layer)
__device__ float g_q[E_NN * HDD];
__device__ float g_k[F_NN * HDD];
__device__ float g_v[F_NN * HDD];
__device__ float g_ep[M_NN * HDD];
__device__ float g_alpha[M_NN * 3];
__device__ float g_amax[E_NN * 3];
__device__ float g_den[E_NN * 3];
__device__ float g_seg[E_NN * HDD];

// ---------------- small utility kernels ----------------
__global__ void fill_kernel(float* __restrict__ p, int n, float v) {
    int t = blockIdx.x * blockDim.x + threadIdx.x;
    if (t < n) p[t] = v;
}

// vector global reduction (sm_90+)
__device__ __forceinline__ void redAdd4(float* addr, float a, float b, float c, float d) {
    asm volatile("red.global.add.v4.f32 [%0], {%1,%2,%3,%4};"
                 :: "l"(addr), "f"(a), "f"(b), "f"(c), "f"(d) : "memory");
}

// order-preserving float->uint key for atomicMax
__device__ __forceinline__ unsigned fkey(float f) {
    int i = __float_as_int(f);
    return (i >= 0) ? ((unsigned)i | 0x80000000u) : (unsigned)(~i);
}
__device__ __forceinline__ float funkey(unsigned key) {
    return (key & 0x80000000u) ? __uint_as_float(key & 0x7FFFFFFFu)
                               : __uint_as_float(~key);
}

// h_aggr[f] += h_dE[e] * sgn  over cobdry edges. One warp per edge.
__global__ void scatter_aggr_kernel(const float* __restrict__ hE,
                                    const int* __restrict__ cob,
                                    float* __restrict__ haggr) {
    int t = blockIdx.x * blockDim.x + threadIdx.x;
    int e = t >> 5;
    if (e >= M_NN) return;
    int lane = t & 31;
    int ecol = cob[e * 3 + 0];
    int fcol = cob[e * 3 + 1];
    float s = (float)cob[e * 3 + 2];
    float4 v4 = ((const float4*)(hE + (size_t)ecol * DD))[lane];
    redAdd4(haggr + (size_t)fcol * DD + lane * 4, s * v4.x, s * v4.y, s * v4.z, s * v4.w);
}

// ---------------- BF16x3 tensor-core GEMM (pipelined, multi-output) ----------------
// C[M,N] = A[M,128] @ B[128,N] (+bias) (+=C) per segment (blockIdx.x).
// Operands split hi=bf16(x), lo=bf16(x-hi); 3 MMAs (hh, hl, lh) of m16n8k16
// give ~2^-18 per-product accuracy. cp.async double-buffered staging.

__device__ __forceinline__ uint32_t bf2(float e0, float e1) {  // e0 -> low half
    __nv_bfloat162 t = __floats2bfloat162_rn(e0, e1);
    return *(uint32_t*)&t;
}

__device__ __forceinline__ void mma_bf16(float* d,
                                         uint32_t a0, uint32_t a1, uint32_t a2, uint32_t a3,
                                         uint32_t b0, uint32_t b1) {
    asm volatile(
        "mma.sync.aligned.m16n8k16.row.col.f32.bf16.bf16.f32 "
        "{%0,%1,%2,%3}, {%4,%5,%6,%7}, {%8,%9}, {%0,%1,%2,%3};\n"
        : "+f"(d[0]), "+f"(d[1]), "+f"(d[2]), "+f"(d[3])
        : "r"(a0), "r"(a1), "r"(a2), "r"(a3), "r"(b0), "r"(b1));
}

__device__ __forceinline__ void cp16(void* smemDst, const void* gsrc) {
    uint32_t s = (uint32_t)__cvta_generic_to_shared(smemDst);
    asm volatile("cp.async.ca.shared.global [%0], [%1], 16;\n" :: "r"(s), "l"(gsrc));
}
#define CP_COMMIT() asm volatile("cp.async.commit_group;\n")
#define CP_WAIT(n)  asm volatile("cp.async.wait_group %0;\n" :: "n"(n))

#define BM 128
#define BN 128
#define BK 16
#define KP 8        // k-pairs per BK
#define SPAD 136    // row stride (u32); (qid*136 + grp) % 32 = qid*8+grp -> conflict-free frags
#define TILE_U32 (KP * SPAD)                     // 1088
#define SMEM_TILES_BYTES (4 * TILE_U32 * 4)      // 17408
#define SMEM_STG_BYTES   (2 * 2 * 256 * 16 * 2)  // stgA + stgB = 32768
#define GEMM_SMEM (SMEM_TILES_BYTES + SMEM_STG_BYTES)  // 50176

struct GSegs {
    const float* B[4];
    const float* bias[4];
    float* C[4];
    int N[4];
    int acc[4];
    int start[4];
    int nseg;
};

__global__ __launch_bounds__(256, 2) void gemm_multi(
    const float* __restrict__ A, int M,
    const int* __restrict__ aIdx, int aCol, int aSgnCol,
    GSegs segs)
{
    extern __shared__ char smem[];
    uint32_t (*AsH)[SPAD] = (uint32_t(*)[SPAD])(smem);
    uint32_t (*AsL)[SPAD] = (uint32_t(*)[SPAD])(smem + TILE_U32 * 4);
    uint32_t (*BsH)[SPAD] = (uint32_t(*)[SPAD])(smem + TILE_U32 * 8);
    uint32_t (*BsL)[SPAD] = (uint32_t(*)[SPAD])(smem + TILE_U32 * 12);
    float4* stgA = (float4*)(smem + SMEM_TILES_BYTES);           // [2][2][256]
    float4* stgB = (float4*)(smem + SMEM_TILES_BYTES + 16384);   // [2][2][256]

    const int tid = threadIdx.x;
    const int lane = tid & 31;
    const int warp = tid >> 5;
    const int warp_m = warp & 1;
    const int warp_n = warp >> 1;
    const int row0 = blockIdx.y * BM;

    // segment resolution
    int s = 0;
#pragma unroll
    for (int t = 1; t < 4; t++)
        if (t < segs.nseg && (int)blockIdx.x >= segs.start[t]) s = t;
    const float* Bp = segs.B[s];
    const float* bias = segs.bias[s];
    float* C = segs.C[s];
    const int N = segs.N[s];
    const int accum = segs.acc[s];
    const int col0 = (blockIdx.x - segs.start[s]) * BN;

    const int grp = lane >> 2;
    const int qid = lane & 3;

    // loader assignments
    const int a_kq = tid & 3;        // k float4 within BK (4 consecutive k = 2 pairs)
    const int a_r0 = tid >> 2;       // row 0..63 (+64 second)
    const int b_cq = tid & 31;       // n float4
    const int b_a  = tid >> 5;       // k-pair 0..7 (rows 2a, 2a+1)

    // resolve A rows (gather + sign; OOB rows -> row 0 with sign 0)
    int ar[2];
    float asgn[2];
#pragma unroll
    for (int i = 0; i < 2; i++) {
        int gr = row0 + a_r0 + i * 64;
        if (gr < M) {
            if (aIdx) {
                ar[i] = aIdx[(size_t)gr * 3 + aCol];
                asgn[i] = (aSgnCol >= 0) ? (float)aIdx[(size_t)gr * 3 + aSgnCol] : 1.0f;
            } else {
                ar[i] = gr;
                asgn[i] = 1.0f;
            }
        } else {
            ar[i] = 0;
            asgn[i] = 0.0f;
        }
    }

    float acc[4][4][4];
#pragma unroll
    for (int i = 0; i < 4; i++)
#pragma unroll
        for (int j = 0; j < 4; j++)
#pragma unroll
            for (int r = 0; r < 4; r++) acc[i][j][r] = 0.f;

    auto stage = [&](int st, int k0) {
#pragma unroll
        for (int i = 0; i < 2; i++)
            cp16(&stgA[(st * 2 + i) * 256 + tid],
                 A + (size_t)ar[i] * 128 + k0 + a_kq * 4);
        cp16(&stgB[(st * 2 + 0) * 256 + tid],
             Bp + (size_t)(k0 + 2 * b_a) * N + col0 + b_cq * 4);
        cp16(&stgB[(st * 2 + 1) * 256 + tid],
             Bp + (size_t)(k0 + 2 * b_a + 1) * N + col0 + b_cq * 4);
    };

    int st = 0;
    stage(0, 0);
    CP_COMMIT();

    for (int k0 = 0; k0 < 128; k0 += BK) {
        if (k0 + BK < 128) {
            stage(st ^ 1, k0 + BK);
            CP_COMMIT();
            CP_WAIT(1);
        } else {
            CP_WAIT(0);
        }

        // convert own staged data into hi/lo bf16 tiles
#pragma unroll
        for (int i = 0; i < 2; i++) {
            float4 va = stgA[(st * 2 + i) * 256 + tid];
            float v0 = va.x * asgn[i], v1 = va.y * asgn[i];
            float v2 = va.z * asgn[i], v3 = va.w * asgn[i];
            int r = a_r0 + i * 64;
            float h0 = __bfloat162float(__float2bfloat16_rn(v0));
            float h1 = __bfloat162float(__float2bfloat16_rn(v1));
            float h2 = __bfloat162float(__float2bfloat16_rn(v2));
            float h3 = __bfloat162float(__float2bfloat16_rn(v3));
            AsH[a_kq * 2 + 0][r] = bf2(h0, h1);
            AsH[a_kq * 2 + 1][r] = bf2(h2, h3);
            AsL[a_kq * 2 + 0][r] = bf2(v0 - h0, v1 - h1);
            AsL[a_kq * 2 + 1][r] = bf2(v2 - h2, v3 - h3);
        }
        {
            float4 r0 = stgB[(st * 2 + 0) * 256 + tid];  // k even row
            float4 r1 = stgB[(st * 2 + 1) * 256 + tid];  // k odd row
            float e0[4] = {r0.x, r0.y, r0.z, r0.w};
            float e1[4] = {r1.x, r1.y, r1.z, r1.w};
            uint4 hv, lv;
            uint32_t* hp = (uint32_t*)&hv;
            uint32_t* lp = (uint32_t*)&lv;
#pragma unroll
            for (int t = 0; t < 4; t++) {
                float h0 = __bfloat162float(__float2bfloat16_rn(e0[t]));
                float h1 = __bfloat162float(__float2bfloat16_rn(e1[t]));
                hp[t] = bf2(h0, h1);
                lp[t] = bf2(e0[t] - h0, e1[t] - h1);
            }
            *(uint4*)&BsH[b_a][b_cq * 4] = hv;
            *(uint4*)&BsL[b_a][b_cq * 4] = lv;
        }
        __syncthreads();

        // fragments: m16n8k16, A row-major, B col-major
        uint32_t afH[4][4], afL[4][4];
        uint32_t bfH[4][2], bfL[4][2];
#pragma unroll
        for (int i = 0; i < 4; i++) {
            int mb = warp_m * 64 + i * 16;
            afH[i][0] = AsH[qid][mb + grp];
            afH[i][1] = AsH[qid][mb + grp + 8];
            afH[i][2] = AsH[qid + 4][mb + grp];
            afH[i][3] = AsH[qid + 4][mb + grp + 8];
            afL[i][0] = AsL[qid][mb + grp];
            afL[i][1] = AsL[qid][mb + grp + 8];
            afL[i][2] = AsL[qid + 4][mb + grp];
            afL[i][3] = AsL[qid + 4][mb + grp + 8];
        }
#pragma unroll
        for (int j = 0; j < 4; j++) {
            int nb = warp_n * 32 + j * 8;
            bfH[j][0] = BsH[qid][nb + grp];
            bfH[j][1] = BsH[qid + 4][nb + grp];
            bfL[j][0] = BsL[qid][nb + grp];
            bfL[j][1] = BsL[qid + 4][nb + grp];
        }
#pragma unroll
        for (int i = 0; i < 4; i++)
#pragma unroll
            for (int j = 0; j < 4; j++) {
                mma_bf16(acc[i][j], afH[i][0], afH[i][1], afH[i][2], afH[i][3],
                         bfH[j][0], bfH[j][1]);
                mma_bf16(acc[i][j], afH[i][0], afH[i][1], afH[i][2], afH[i][3],
                         bfL[j][0], bfL[j][1]);
                mma_bf16(acc[i][j], afL[i][0], afL[i][1], afL[i][2], afL[i][3],
                         bfH[j][0], bfH[j][1]);
            }
        __syncthreads();
        st ^= 1;
    }

    // epilogue
#pragma unroll
    for (int i = 0; i < 4; i++) {
        int row = row0 + warp_m * 64 + i * 16 + grp;
#pragma unroll
        for (int j = 0; j < 4; j++) {
            int col = col0 + warp_n * 32 + j * 8 + qid * 2;
#pragma unroll
            for (int half = 0; half < 2; half++) {
                int r = row + half * 8;
                if (r >= M) continue;
                float2 res;
                res.x = acc[i][j][half * 2 + 0];
                res.y = acc[i][j][half * 2 + 1];
                if (bias) {
                    res.x += bias[col + 0];
                    res.y += bias[col + 1];
                }
                float2* cp = (float2*)(C + (size_t)r * N + col);
                if (accum) {
                    float2 old = *cp;
                    res.x += old.x;
                    res.y += old.y;
                }
                *cp = res;
            }
        }
    }
}

// ---------------- attention kernels ----------------
__global__ void attn_alpha_kernel(const float* __restrict__ q,
                                  const float* __restrict__ k,
                                  const float* __restrict__ ep,
                                  const int* __restrict__ idx,
                                  int srcCol, int dstCol, int E,
                                  float* __restrict__ alpha,
                                  float* __restrict__ amax) {
    int e = blockIdx.x * 8 + (threadIdx.x >> 5);
    if (e >= E) return;
    int lane = threadIdx.x & 31;
    int src = idx[e * 3 + srcCol];
    int dst = idx[e * 3 + dstCol];
    const float4* qp = (const float4*)(q + (size_t)dst * HDD);
    const float4* kp = (const float4*)(k + (size_t)src * HDD);
    const float4* epp = (const float4*)(ep + (size_t)e * HDD);
#pragma unroll
    for (int h = 0; h < 3; h++) {
        float4 qv = qp[h * 32 + lane];
        float4 kv = kp[h * 32 + lane];
        float4 ev = epp[h * 32 + lane];
        float s = qv.x * (kv.x + ev.x) + qv.y * (kv.y + ev.y) +
                  qv.z * (kv.z + ev.z) + qv.w * (kv.w + ev.w);
#pragma unroll
        for (int o = 16; o > 0; o >>= 1) s += __shfl_xor_sync(0xffffffffu, s, o);
        if (lane == 0) {
            s *= 0.08838834764831845f;  // 1/sqrt(128)
            alpha[e * 3 + h] = s;
            atomicMax((unsigned int*)&amax[dst * 3 + h], fkey(s));
        }
    }
}

__global__ void attn_expden_kernel(const int* __restrict__ idx, int dstCol, int E,
                                   float* __restrict__ alpha,
                                   const float* __restrict__ amax,
                                   float* __restrict__ den) {
    int t = blockIdx.x * blockDim.x + threadIdx.x;
    if (t >= E * 3) return;
    int e = t / 3, h = t - 3 * e;
    int dst = idx[e * 3 + dstCol];
    float am = funkey(__float_as_uint(amax[dst * 3 + h]));
    float ex = expf(alpha[t] - am);
    alpha[t] = ex;
    atomicAdd(&den[dst * 3 + h], ex);
}

__global__ void attn_scatter_kernel(const float* __restrict__ v,
                                    const float* __restrict__ ep,
                                    const int* __restrict__ idx,
                                    int srcCol, int dstCol, int E,
                                    const float* __restrict__ alpha,
                                    const float* __restrict__ den,
                                    float* __restrict__ seg) {
    int e = blockIdx.x * 8 + (threadIdx.x >> 5);
    if (e >= E) return;
    int lane = threadIdx.x & 31;
    int src = idx[e * 3 + srcCol];
    int dst = idx[e * 3 + dstCol];
    const float4* vp = (const float4*)(v + (size_t)src * HDD);
    const float4* epp = (const float4*)(ep + (size_t)e * HDD);
    float* op = seg + (size_t)dst * HDD;
#pragma unroll
    for (int h = 0; h < 3; h++) {
        float w = alpha[e * 3 + h] / (den[dst * 3 + h] + 1e-16f);
        float4 vv = vp[h * 32 + lane];
        float4 ev = epp[h * 32 + lane];
        int c = h * 128 + lane * 4;
        redAdd4(op + c, w * (vv.x + ev.x), w * (vv.y + ev.y),
                        w * (vv.z + ev.z), w * (vv.w + ev.w));
    }
}

// out = mean over heads (+ residual hin) (+ ws projection)
__global__ void combine_kernel(const float* __restrict__ seg,
                               const float* __restrict__ hin,
                               const float* __restrict__ ws,
                               float* __restrict__ out, int n) {
    int t = blockIdx.x * blockDim.x + threadIdx.x;
    if (t >= n * DD) return;
    int node = t >> 7, d = t & 127;
    const float* s = seg + (size_t)node * HDD;
    float m = (s[d] + s[128 + d] + s[256 + d]) * (1.0f / 3.0f);
    if (hin) m += hin[t];
    if (ws) m += ws[t];
    out[t] = m;
}

// ---------------- host orchestration ----------------
static inline int cdiv(int a, int b) { return (a + b - 1) / b; }

static GSegs mk1(const float* B, const float* bias, float* C, int N, int acc) {
    GSegs s = {};
    s.B[0] = B; s.bias[0] = bias; s.C[0] = C; s.N[0] = N; s.acc[0] = acc;
    s.start[0] = 0; s.nseg = 1;
    return s;
}

extern "C" void kernel_launch(void* const* d_in, const int* in_sizes, int n_in,
                              void* d_out, int out_size) {
    const float* h_dE = (const float*)d_in[0];
    const float* h_dF = (const float*)d_in[1];
    const int* cob = (const int*)d_in[2];
    const int* nn = (const int*)d_in[3];
    const float* aggr_W = (const float*)d_in[4];
    const float* aggr_b = (const float*)d_in[5];
    const float* ctr_W = (const float*)d_in[6];
    const float* ctr_b = (const float*)d_in[7];
    const float* f_Wq = (const float*)d_in[8];
    const float* f_bq = (const float*)d_in[9];
    const float* f_Wk = (const float*)d_in[10];
    const float* f_bk = (const float*)d_in[11];
    const float* f_Wv = (const float*)d_in[12];
    const float* f_bv = (const float*)d_in[13];
    const float* f_We = (const float*)d_in[14];
    const float* f_Ws = (const float*)d_in[15];
    const float* f_bs = (const float*)d_in[16];
    const float* e_Wq = (const float*)d_in[17];
    const float* e_bq = (const float*)d_in[18];
    const float* e_Wk = (const float*)d_in[19];
    const float* e_bk = (const float*)d_in[20];
    const float* e_Wv = (const float*)d_in[21];
    const float* e_bv = (const float*)d_in[22];
    const float* e_We = (const float*)d_in[23];
    const float* e_Ws = (const float*)d_in[24];
    const float* e_bs = (const float*)d_in[25];
    float* out = (float*)d_out;

    cudaFuncSetAttribute(gemm_multi, cudaFuncAttributeMaxDynamicSharedMemorySize, GEMM_SMEM);

    float *h0, *h1, *haggr, *wsE, *q, *k, *v, *ep, *alpha, *amax, *den, *seg;
    cudaGetSymbolAddress((void**)&h0, g_h0);
    cudaGetSymbolAddress((void**)&h1, g_h1);
    cudaGetSymbolAddress((void**)&haggr, g_haggr);
    cudaGetSymbolAddress((void**)&wsE, g_wsE);
    cudaGetSymbolAddress((void**)&q, g_q);
    cudaGetSymbolAddress((void**)&k, g_k);
    cudaGetSymbolAddress((void**)&v, g_v);
    cudaGetSymbolAddress((void**)&ep, g_ep);
    cudaGetSymbolAddress((void**)&alpha, g_alpha);
    cudaGetSymbolAddress((void**)&amax, g_amax);
    cudaGetSymbolAddress((void**)&den, g_den);
    cudaGetSymbolAddress((void**)&seg, g_seg);

    const int FY = cdiv(F_NN, 128);   // 196
    const int EY = cdiv(E_NN, 128);   // 391
    const int PY = cdiv(P_NN, 128);   // 586
    const int MY = cdiv(M_NN, 128);   // 782

    // 1) h_aggr = segment_sum(h_dE[e]*sgn over f)
    fill_kernel<<<cdiv(F_NN * DD, 256), 256>>>(haggr, F_NN * DD, 0.f);
    scatter_aggr_kernel<<<cdiv(M_NN * 32, 256), 256>>>(h_dE, cob, haggr);

    // 2) h = h_aggr@aggr_W + aggr_b + h_dF@ctr_W + ctr_b
    {
        GSegs s1 = mk1(aggr_W, aggr_b, h0, 128, 0);
        gemm_multi<<<dim3(1, FY), 256, GEMM_SMEM>>>(haggr, F_NN, nullptr, 0, -1, s1);
        GSegs s2 = mk1(ctr_W, ctr_b, h0, 128, 1);
        gemm_multi<<<dim3(1, FY), 256, GEMM_SMEM>>>(h_dF, F_NN, nullptr, 0, -1, s2);
    }

    float* hcur = h0;
    float* hnext = h1;
    for (int l = 0; l < 3; l++) {
        const float* Wq = f_Wq + (size_t)l * 128 * 384;
        const float* bq = f_bq + (size_t)l * 384;
        const float* Wk = f_Wk + (size_t)l * 128 * 384;
        const float* bk = f_bk + (size_t)l * 384;
        const float* Wv = f_Wv + (size_t)l * 128 * 384;
        const float* bv = f_bv + (size_t)l * 384;
        const float* We = f_We + (size_t)l * 128 * 384;
        const float* Ws = f_Ws + (size_t)l * 128 * 128;
        const float* bs = f_bs + (size_t)l * 128;

        // fused q,k,v,Ws GEMM over hcur
        GSegs sq = {};
        sq.B[0] = Wq; sq.bias[0] = bq; sq.C[0] = q;     sq.N[0] = 384; sq.acc[0] = 0; sq.start[0] = 0;
        sq.B[1] = Wk; sq.bias[1] = bk; sq.C[1] = k;     sq.N[1] = 384; sq.acc[1] = 0; sq.start[1] = 3;
        sq.B[2] = Wv; sq.bias[2] = bv; sq.C[2] = v;     sq.N[2] = 384; sq.acc[2] = 0; sq.start[2] = 6;
        sq.B[3] = Ws; sq.bias[3] = bs; sq.C[3] = haggr; sq.N[3] = 128; sq.acc[3] = 0; sq.start[3] = 9;
        sq.nseg = 4;
        gemm_multi<<<dim3(10, FY), 256, GEMM_SMEM>>>(hcur, F_NN, nullptr, 0, -1, sq);

        // ep = h_dE[nn[:,2]] @ We  (gather fused into A load)
        GSegs se = mk1(We, nullptr, ep, 384, 0);
        gemm_multi<<<dim3(3, PY), 256, GEMM_SMEM>>>(h_dE, P_NN, nn, 2, -1, se);

        fill_kernel<<<cdiv(F_NN * 3, 256), 256>>>(amax, F_NN * 3, 0.f);
        fill_kernel<<<cdiv(F_NN * 3, 256), 256>>>(den, F_NN * 3, 0.f);
        fill_kernel<<<cdiv(F_NN * HDD, 256), 256>>>(seg, F_NN * HDD, 0.f);

        attn_alpha_kernel<<<cdiv(P_NN, 8), 256>>>(q, k, ep, nn, 0, 1, P_NN, alpha, amax);
        attn_expden_kernel<<<cdiv(P_NN * 3, 256), 256>>>(nn, 1, P_NN, alpha, amax, den);
        attn_scatter_kernel<<<cdiv(P_NN, 8), 256>>>(v, ep, nn, 0, 1, P_NN, alpha, den, seg);

        combine_kernel<<<cdiv(F_NN * DD, 256), 256>>>(seg, hcur, haggr, hnext, F_NN);

        float* tmp = hcur; hcur = hnext; hnext = tmp;
    }

    // final cross attention: F -> E over cobdry edges (src=f_col(1), dst=e_col(0))
    {
        // q (E rows) + Ws (E rows) fused
        GSegs sq = {};
        sq.B[0] = e_Wq; sq.bias[0] = e_bq; sq.C[0] = q;   sq.N[0] = 384; sq.acc[0] = 0; sq.start[0] = 0;
        sq.B[1] = e_Ws; sq.bias[1] = e_bs; sq.C[1] = wsE; sq.N[1] = 128; sq.acc[1] = 0; sq.start[1] = 3;
        sq.nseg = 2;
        gemm_multi<<<dim3(4, EY), 256, GEMM_SMEM>>>(h_dE, E_NN, nullptr, 0, -1, sq);

        // k + v (F rows) fused
        GSegs skv = {};
        skv.B[0] = e_Wk; skv.bias[0] = e_bk; skv.C[0] = k; skv.N[0] = 384; skv.acc[0] = 0; skv.start[0] = 0;
        skv.B[1] = e_Wv; skv.bias[1] = e_bv; skv.C[1] = v; skv.N[1] = 384; skv.acc[1] = 0; skv.start[1] = 3;
        skv.nseg = 2;
        gemm_multi<<<dim3(6, FY), 256, GEMM_SMEM>>>(hcur, F_NN, nullptr, 0, -1, skv);

        // ep = (hcur[cob[:,1]] * sgn) @ e_We  (gather+sign fused)
        GSegs se = mk1(e_We, nullptr, ep, 384, 0);
        gemm_multi<<<dim3(3, MY), 256, GEMM_SMEM>>>(hcur, M_NN, cob, 1, 2, se);
    }

    fill_kernel<<<cdiv(E_NN * 3, 256), 256>>>(amax, E_NN * 3, 0.f);
    fill_kernel<<<cdiv(E_NN * 3, 256), 256>>>(den, E_NN * 3, 0.f);
    fill_kernel<<<cdiv(E_NN * HDD, 256), 256>>>(seg, E_NN * HDD, 0.f);

    attn_alpha_kernel<<<cdiv(M_NN, 8), 256>>>(q, k, ep, cob, 1, 0, M_NN, alpha, amax);
    attn_expden_kernel<<<cdiv(M_NN * 3, 256), 256>>>(cob, 0, M_NN, alpha, amax, den);
    attn_scatter_kernel<<<cdiv(M_NN, 8), 256>>>(v, ep, cob, 1, 0, M_NN, alpha, den, seg);

    combine_kernel<<<cdiv(E_NN * DD, 256), 256>>>(seg, nullptr, wsE, out, E_NN);
}

// round 7
// speedup vs baseline: 1.5979x; 1.0024x over previous
#include <cuda_runtime.h>
#include <cuda_bf16.h>
#include <math.h>
#include <stdint.h>

#define E_NN 50000
#define F_NN 25000
#define M_NN 100000
#define P_NN 75000
#define DD   128
#define HDD  384

// ---------------- scratch (device globals; no allocation allowed) ----------------
__device__ float g_h0[F_NN * DD];
__device__ float g_h1[F_NN * DD];
__device__ float g_haggr[F_NN * DD];   // init aggr; later reused as Ws output (F)
__device__ float g_wsE[E_NN * DD];     // Ws output (E, final layer)
__device__ float g_q[E_NN * HDD];
__device__ float g_k[F_NN * HDD];
__device__ float g_v[F_NN * HDD];
__device__ float g_ep[M_NN * HDD];
__device__ float g_alpha[M_NN * 3];
__device__ float g_amax[E_NN * 3];
__device__ float g_den[E_NN * 3];
__device__ float g_seg[E_NN * HDD];
// preconverted paired-bf16 operands
__device__ uint32_t g_apkH[64 * M_NN];     // activations hi, [m][64] layout
__device__ uint32_t g_apkL[64 * M_NN];     // activations lo
__device__ uint32_t g_eapkH[64 * P_NN];    // gathered ea (layer-invariant)
__device__ uint32_t g_eapkL[64 * P_NN];
__device__ uint32_t g_wpkH[448 * 1024];    // all weights hi, [kpair][N] per matrix
__device__ uint32_t g_wpkL[448 * 1024];

// ---------------- small utility kernels ----------------
__global__ void fill_kernel(float* __restrict__ p, int n, float v) {
    int t = blockIdx.x * blockDim.x + threadIdx.x;
    if (t < n) p[t] = v;
}

__device__ __forceinline__ void redAdd4(float* addr, float a, float b, float c, float d) {
    asm volatile("red.global.add.v4.f32 [%0], {%1,%2,%3,%4};"
                 :: "l"(addr), "f"(a), "f"(b), "f"(c), "f"(d) : "memory");
}

__device__ __forceinline__ unsigned fkey(float f) {
    int i = __float_as_int(f);
    return (i >= 0) ? ((unsigned)i | 0x80000000u) : (unsigned)(~i);
}
__device__ __forceinline__ float funkey(unsigned key) {
    return (key & 0x80000000u) ? __uint_as_float(key & 0x7FFFFFFFu)
                               : __uint_as_float(~key);
}

__global__ void scatter_aggr_kernel(const float* __restrict__ hE,
                                    const int* __restrict__ cob,
                                    float* __restrict__ haggr) {
    int t = blockIdx.x * blockDim.x + threadIdx.x;
    int e = t >> 5;
    if (e >= M_NN) return;
    int lane = t & 31;
    int ecol = cob[e * 3 + 0];
    int fcol = cob[e * 3 + 1];
    float s = (float)cob[e * 3 + 2];
    float4 v4 = ((const float4*)(hE + (size_t)ecol * DD))[lane];
    redAdd4(haggr + (size_t)fcol * DD + lane * 4, s * v4.x, s * v4.y, s * v4.z, s * v4.w);
}

// ---------------- bf16 hi/lo packing helpers ----------------
__device__ __forceinline__ uint32_t bf2(float e0, float e1) {  // e0 -> low half
    __nv_bfloat162 t = __floats2bfloat162_rn(e0, e1);
    return *(uint32_t*)&t;
}

// activations: A[M][128] float (+optional gather/sign) -> Apk[m][64] u32 hi/lo
__global__ void conv_act_kernel(const float* __restrict__ A, int M,
                                const int* __restrict__ idx, int col, int sgnCol,
                                uint32_t* __restrict__ outH,
                                uint32_t* __restrict__ outL) {
    int t = blockIdx.x * blockDim.x + threadIdx.x;
    int r = t >> 5;
    if (r >= M) return;
    int lane = t & 31;
    int src = r;
    float sgn = 1.0f;
    if (idx) {
        src = idx[(size_t)r * 3 + col];
        if (sgnCol >= 0) sgn = (float)idx[(size_t)r * 3 + sgnCol];
    }
    float4 v = ((const float4*)(A + (size_t)src * 128))[lane];
    v.x *= sgn; v.y *= sgn; v.z *= sgn; v.w *= sgn;
    float h0 = __bfloat162float(__float2bfloat16_rn(v.x));
    float h1 = __bfloat162float(__float2bfloat16_rn(v.y));
    float h2 = __bfloat162float(__float2bfloat16_rn(v.z));
    float h3 = __bfloat162float(__float2bfloat16_rn(v.w));
    size_t o = (size_t)r * 64 + lane * 2;
    outH[o + 0] = bf2(h0, h1);
    outH[o + 1] = bf2(h2, h3);
    outL[o + 0] = bf2(v.x - h0, v.y - h1);
    outL[o + 1] = bf2(v.z - h2, v.w - h3);
}

// weights: W[L][128][N] float -> Wpk[L][kpair][N] u32 hi/lo
__global__ void conv_w_kernel(const float* __restrict__ W, int N, int L,
                              uint32_t* __restrict__ outH,
                              uint32_t* __restrict__ outL) {
    int t = blockIdx.x * blockDim.x + threadIdx.x;
    int total = L * 64 * N;
    if (t >= total) return;
    int l = t / (64 * N);
    int rem = t - l * 64 * N;
    int p = rem / N;
    int n = rem - p * N;
    const float* src = W + ((size_t)l * 128 + 2 * p) * N + n;
    float v0 = src[0];
    float v1 = src[N];
    float h0 = __bfloat162float(__float2bfloat16_rn(v0));
    float h1 = __bfloat162float(__float2bfloat16_rn(v1));
    outH[t] = bf2(h0, h1);
    outL[t] = bf2(v0 - h0, v1 - h1);
}

// ---------------- BF16x3 tensor-core GEMM (preconverted, 3-stage pipeline) ----------------
__device__ __forceinline__ void mma_bf16(float* d,
                                         uint32_t a0, uint32_t a1, uint32_t a2, uint32_t a3,
                                         uint32_t b0, uint32_t b1) {
    asm volatile(
        "mma.sync.aligned.m16n8k16.row.col.f32.bf16.bf16.f32 "
        "{%0,%1,%2,%3}, {%4,%5,%6,%7}, {%8,%9}, {%0,%1,%2,%3};\n"
        : "+f"(d[0]), "+f"(d[1]), "+f"(d[2]), "+f"(d[3])
        : "r"(a0), "r"(a1), "r"(a2), "r"(a3), "r"(b0), "r"(b1));
}

__device__ __forceinline__ void cp16(void* smemDst, const void* gsrc) {
    uint32_t s = (uint32_t)__cvta_generic_to_shared(smemDst);
    asm volatile("cp.async.ca.shared.global [%0], [%1], 16;\n" :: "r"(s), "l"(gsrc));
}
#define CP_COMMIT() asm volatile("cp.async.commit_group;\n")
#define CP_WAIT(n)  asm volatile("cp.async.wait_group %0;\n" :: "n"(n))

#define BM 128
#define BN 128
#define STAGES 3
#define ASTRIDE 12                    // u32 per A-tile row (8 used + pad); banks (12g+q)%32 all-distinct
#define BSTRIDE 136                   // u32 per B-tile kpair row (proven conflict-free)
#define A_ST_U32 (128 * ASTRIDE)      // 1536
#define B_ST_U32 (8 * BSTRIDE)        // 1088
#define GEMM_SMEM (STAGES * (2 * A_ST_U32 + 2 * B_ST_U32) * 4)  // 62976

struct GSegs {
    const uint32_t* BH[4];
    const uint32_t* BL[4];
    const float* bias[4];
    float* C[4];
    int N[4];
    int acc[4];
    int start[4];
    int nseg;
};

__global__ __launch_bounds__(256, 2) void gemm_multi(
    const uint32_t* __restrict__ apkH, const uint32_t* __restrict__ apkL,
    int M, GSegs segs)
{
    extern __shared__ uint32_t smu[];
    uint32_t* AsH = smu;
    uint32_t* AsL = smu + STAGES * A_ST_U32;
    uint32_t* BsH = smu + 2 * STAGES * A_ST_U32;
    uint32_t* BsL = BsH + STAGES * B_ST_U32;

    const int tid = threadIdx.x;
    const int lane = tid & 31;
    const int warp = tid >> 5;
    const int warp_m = warp & 1;
    const int warp_n = warp >> 1;
    const int row0 = blockIdx.y * BM;

    // segment resolution
    int s = 0;
#pragma unroll
    for (int t = 1; t < 4; t++)
        if (t < segs.nseg && (int)blockIdx.x >= segs.start[t]) s = t;
    const uint32_t* BHp = segs.BH[s];
    const uint32_t* BLp = segs.BL[s];
    const float* bias = segs.bias[s];
    float* C = segs.C[s];
    const int N = segs.N[s];
    const int accum = segs.acc[s];
    const int col0 = (blockIdx.x - segs.start[s]) * BN;

    const int grp = lane >> 2;
    const int qid = lane & 3;

    // loader assignments
    const int a_m = tid >> 1;        // tile row 0..127
    const int a_c = tid & 1;         // 16B chunk within row (kpairs 0-3 / 4-7)
    const int b_kp = tid >> 5;       // kpair row 0..7
    const int b_ch = tid & 31;       // 16B chunk along n

    const int arow = (row0 + a_m < M) ? (row0 + a_m) : (M - 1);
    const uint32_t* gAH = apkH + (size_t)arow * 64 + a_c * 4;
    const uint32_t* gAL = apkL + (size_t)arow * 64 + a_c * 4;
    const uint32_t* gBH = BHp + (size_t)b_kp * N + col0 + b_ch * 4;
    const uint32_t* gBL = BLp + (size_t)b_kp * N + col0 + b_ch * 4;

    float acc[4][4][4];
#pragma unroll
    for (int i = 0; i < 4; i++)
#pragma unroll
        for (int j = 0; j < 4; j++)
#pragma unroll
            for (int r = 0; r < 4; r++) acc[i][j][r] = 0.f;

    auto stage = [&](int slot, int kp0) {
        uint32_t* aH = AsH + slot * A_ST_U32 + a_m * ASTRIDE + a_c * 4;
        uint32_t* aL = AsL + slot * A_ST_U32 + a_m * ASTRIDE + a_c * 4;
        cp16(aH, gAH + kp0);
        cp16(aL, gAL + kp0);
        uint32_t* bH = BsH + slot * B_ST_U32 + b_kp * BSTRIDE + b_ch * 4;
        uint32_t* bL = BsL + slot * B_ST_U32 + b_kp * BSTRIDE + b_ch * 4;
        cp16(bH, gBH + (size_t)kp0 * N);
        cp16(bL, gBL + (size_t)kp0 * N);
    };

    stage(0, 0);
    CP_COMMIT();
    stage(1, 8);
    CP_COMMIT();

    for (int it = 0; it < 8; it++) {
        CP_WAIT(1);
        __syncthreads();
        const int buf = it % STAGES;
        const uint32_t* cAH = AsH + buf * A_ST_U32;
        const uint32_t* cAL = AsL + buf * A_ST_U32;
        const uint32_t* cBH = BsH + buf * B_ST_U32;
        const uint32_t* cBL = BsL + buf * B_ST_U32;

        uint32_t afH[4][4], afL[4][4];
        uint32_t bfH[4][2], bfL[4][2];
#pragma unroll
        for (int i = 0; i < 4; i++) {
            int mr = warp_m * 64 + i * 16 + grp;
            afH[i][0] = cAH[mr * ASTRIDE + qid];
            afH[i][1] = cAH[(mr + 8) * ASTRIDE + qid];
            afH[i][2] = cAH[mr * ASTRIDE + qid + 4];
            afH[i][3] = cAH[(mr + 8) * ASTRIDE + qid + 4];
            afL[i][0] = cAL[mr * ASTRIDE + qid];
            afL[i][1] = cAL[(mr + 8) * ASTRIDE + qid];
            afL[i][2] = cAL[mr * ASTRIDE + qid + 4];
            afL[i][3] = cAL[(mr + 8) * ASTRIDE + qid + 4];
        }
#pragma unroll
        for (int j = 0; j < 4; j++) {
            int nb = warp_n * 32 + j * 8 + grp;
            bfH[j][0] = cBH[qid * BSTRIDE + nb];
            bfH[j][1] = cBH[(qid + 4) * BSTRIDE + nb];
            bfL[j][0] = cBL[qid * BSTRIDE + nb];
            bfL[j][1] = cBL[(qid + 4) * BSTRIDE + nb];
        }
#pragma unroll
        for (int i = 0; i < 4; i++)
#pragma unroll
            for (int j = 0; j < 4; j++) {
                mma_bf16(acc[i][j], afH[i][0], afH[i][1], afH[i][2], afH[i][3],
                         bfH[j][0], bfH[j][1]);
                mma_bf16(acc[i][j], afH[i][0], afH[i][1], afH[i][2], afH[i][3],
                         bfL[j][0], bfL[j][1]);
                mma_bf16(acc[i][j], afL[i][0], afL[i][1], afL[i][2], afL[i][3],
                         bfH[j][0], bfH[j][1]);
            }

        int nxt = it + STAGES - 1;
        if (nxt < 8) stage(nxt % STAGES, nxt * 8);
        CP_COMMIT();
    }

    // epilogue
#pragma unroll
    for (int i = 0; i < 4; i++) {
        int row = row0 + warp_m * 64 + i * 16 + grp;
#pragma unroll
        for (int j = 0; j < 4; j++) {
            int col = col0 + warp_n * 32 + j * 8 + qid * 2;
#pragma unroll
            for (int half = 0; half < 2; half++) {
                int r = row + half * 8;
                if (r >= M) continue;
                float2 res;
                res.x = acc[i][j][half * 2 + 0];
                res.y = acc[i][j][half * 2 + 1];
                if (bias) {
                    res.x += bias[col + 0];
                    res.y += bias[col + 1];
                }
                float2* cp = (float2*)(C + (size_t)r * N + col);
                if (accum) {
                    float2 old = *cp;
                    res.x += old.x;
                    res.y += old.y;
                }
                *cp = res;
            }
        }
    }
}

// ---------------- attention kernels ----------------
__global__ void attn_alpha_kernel(const float* __restrict__ q,
                                  const float* __restrict__ k,
                                  const float* __restrict__ ep,
                                  const int* __restrict__ idx,
                                  int srcCol, int dstCol, int E,
                                  float* __restrict__ alpha,
                                  float* __restrict__ amax) {
    int e = blockIdx.x * 8 + (threadIdx.x >> 5);
    if (e >= E) return;
    int lane = threadIdx.x & 31;
    int src = idx[e * 3 + srcCol];
    int dst = idx[e * 3 + dstCol];
    const float4* qp = (const float4*)(q + (size_t)dst * HDD);
    const float4* kp = (const float4*)(k + (size_t)src * HDD);
    const float4* epp = (const float4*)(ep + (size_t)e * HDD);
#pragma unroll
    for (int h = 0; h < 3; h++) {
        float4 qv = qp[h * 32 + lane];
        float4 kv = kp[h * 32 + lane];
        float4 ev = epp[h * 32 + lane];
        float s = qv.x * (kv.x + ev.x) + qv.y * (kv.y + ev.y) +
                  qv.z * (kv.z + ev.z) + qv.w * (kv.w + ev.w);
#pragma unroll
        for (int o = 16; o > 0; o >>= 1) s += __shfl_xor_sync(0xffffffffu, s, o);
        if (lane == 0) {
            s *= 0.08838834764831845f;  // 1/sqrt(128)
            alpha[e * 3 + h] = s;
            atomicMax((unsigned int*)&amax[dst * 3 + h], fkey(s));
        }
    }
}

__global__ void attn_expden_kernel(const int* __restrict__ idx, int dstCol, int E,
                                   float* __restrict__ alpha,
                                   const float* __restrict__ amax,
                                   float* __restrict__ den) {
    int t = blockIdx.x * blockDim.x + threadIdx.x;
    if (t >= E * 3) return;
    int e = t / 3, h = t - 3 * e;
    int dst = idx[e * 3 + dstCol];
    float am = funkey(__float_as_uint(amax[dst * 3 + h]));
    float ex = expf(alpha[t] - am);
    alpha[t] = ex;
    atomicAdd(&den[dst * 3 + h], ex);
}

__global__ void attn_scatter_kernel(const float* __restrict__ v,
                                    const float* __restrict__ ep,
                                    const int* __restrict__ idx,
                                    int srcCol, int dstCol, int E,
                                    const float* __restrict__ alpha,
                                    const float* __restrict__ den,
                                    float* __restrict__ seg) {
    int e = blockIdx.x * 8 + (threadIdx.x >> 5);
    if (e >= E) return;
    int lane = threadIdx.x & 31;
    int src = idx[e * 3 + srcCol];
    int dst = idx[e * 3 + dstCol];
    const float4* vp = (const float4*)(v + (size_t)src * HDD);
    const float4* epp = (const float4*)(ep + (size_t)e * HDD);
    float* op = seg + (size_t)dst * HDD;
#pragma unroll
    for (int h = 0; h < 3; h++) {
        float w = alpha[e * 3 + h] / (den[dst * 3 + h] + 1e-16f);
        float4 vv = vp[h * 32 + lane];
        float4 ev = epp[h * 32 + lane];
        int c = h * 128 + lane * 4;
        redAdd4(op + c, w * (vv.x + ev.x), w * (vv.y + ev.y),
                        w * (vv.z + ev.z), w * (vv.w + ev.w));
    }
}

__global__ void combine_kernel(const float* __restrict__ seg,
                               const float* __restrict__ hin,
                               const float* __restrict__ ws,
                               float* __restrict__ out, int n) {
    int t = blockIdx.x * blockDim.x + threadIdx.x;
    if (t >= n * DD) return;
    int node = t >> 7, d = t & 127;
    const float* s = seg + (size_t)node * HDD;
    float m = (s[d] + s[128 + d] + s[256 + d]) * (1.0f / 3.0f);
    if (hin) m += hin[t];
    if (ws) m += ws[t];
    out[t] = m;
}

// ---------------- host orchestration ----------------
static inline int cdiv(int a, int b) { return (a + b - 1) / b; }

extern "C" void kernel_launch(void* const* d_in, const int* in_sizes, int n_in,
                              void* d_out, int out_size) {
    const float* h_dE = (const float*)d_in[0];
    const float* h_dF = (const float*)d_in[1];
    const int* cob = (const int*)d_in[2];
    const int* nn = (const int*)d_in[3];
    const float* aggr_W = (const float*)d_in[4];
    const float* aggr_b = (const float*)d_in[5];
    const float* ctr_W = (const float*)d_in[6];
    const float* ctr_b = (const float*)d_in[7];
    const float* f_Wq = (const float*)d_in[8];
    const float* f_bq = (const float*)d_in[9];
    const float* f_Wk = (const float*)d_in[10];
    const float* f_bk = (const float*)d_in[11];
    const float* f_Wv = (const float*)d_in[12];
    const float* f_bv = (const float*)d_in[13];
    const float* f_We = (const float*)d_in[14];
    const float* f_Ws = (const float*)d_in[15];
    const float* f_bs = (const float*)d_in[16];
    const float* e_Wq = (const float*)d_in[17];
    const float* e_bq = (const float*)d_in[18];
    const float* e_Wk = (const float*)d_in[19];
    const float* e_bk = (const float*)d_in[20];
    const float* e_Wv = (const float*)d_in[21];
    const float* e_bv = (const float*)d_in[22];
    const float* e_We = (const float*)d_in[23];
    const float* e_Ws = (const float*)d_in[24];
    const float* e_bs = (const float*)d_in[25];
    float* out = (float*)d_out;

    cudaFuncSetAttribute(gemm_multi, cudaFuncAttributeMaxDynamicSharedMemorySize, GEMM_SMEM);

    float *h0, *h1, *haggr, *wsE, *q, *k, *v, *ep, *alpha, *amax, *den, *seg;
    uint32_t *apkH, *apkL, *eapkH, *eapkL, *wpkH, *wpkL;
    cudaGetSymbolAddress((void**)&h0, g_h0);
    cudaGetSymbolAddress((void**)&h1, g_h1);
    cudaGetSymbolAddress((void**)&haggr, g_haggr);
    cudaGetSymbolAddress((void**)&wsE, g_wsE);
    cudaGetSymbolAddress((void**)&q, g_q);
    cudaGetSymbolAddress((void**)&k, g_k);
    cudaGetSymbolAddress((void**)&v, g_v);
    cudaGetSymbolAddress((void**)&ep, g_ep);
    cudaGetSymbolAddress((void**)&alpha, g_alpha);
    cudaGetSymbolAddress((void**)&amax, g_amax);
    cudaGetSymbolAddress((void**)&den, g_den);
    cudaGetSymbolAddress((void**)&seg, g_seg);
    cudaGetSymbolAddress((void**)&apkH, g_apkH);
    cudaGetSymbolAddress((void**)&apkL, g_apkL);
    cudaGetSymbolAddress((void**)&eapkH, g_eapkH);
    cudaGetSymbolAddress((void**)&eapkL, g_eapkL);
    cudaGetSymbolAddress((void**)&wpkH, g_wpkH);
    cudaGetSymbolAddress((void**)&wpkL, g_wpkL);

    const int FY = cdiv(F_NN, 128);   // 196
    const int EY = cdiv(E_NN, 128);   // 391
    const int PY = cdiv(P_NN, 128);   // 586
    const int MY = cdiv(M_NN, 128);   // 782

    // ---- weight conversion offsets (u32 units; 64*N*L per family) ----
    int off = 0;
    auto wreg = [&](int N, int L) { int o = off; off += 64 * N * L; return o; };
    const int o_aggr = wreg(128, 1);
    const int o_ctr  = wreg(128, 1);
    const int o_fq   = wreg(384, 3);
    const int o_fk   = wreg(384, 3);
    const int o_fv   = wreg(384, 3);
    const int o_fwe  = wreg(384, 3);
    const int o_fws  = wreg(128, 3);
    const int o_eq   = wreg(384, 1);
    const int o_ek   = wreg(384, 1);
    const int o_ev   = wreg(384, 1);
    const int o_ewe  = wreg(384, 1);
    const int o_ews  = wreg(128, 1);

    auto convw = [&](const float* W, int N, int L, int o) {
        int tot = L * 64 * N;
        conv_w_kernel<<<cdiv(tot, 256), 256>>>(W, N, L, wpkH + o, wpkL + o);
    };
    convw(aggr_W, 128, 1, o_aggr);
    convw(ctr_W, 128, 1, o_ctr);
    convw(f_Wq, 384, 3, o_fq);
    convw(f_Wk, 384, 3, o_fk);
    convw(f_Wv, 384, 3, o_fv);
    convw(f_We, 384, 3, o_fwe);
    convw(f_Ws, 128, 3, o_fws);
    convw(e_Wq, 384, 1, o_eq);
    convw(e_Wk, 384, 1, o_ek);
    convw(e_Wv, 384, 1, o_ev);
    convw(e_We, 384, 1, o_ewe);
    convw(e_Ws, 128, 1, o_ews);

    // 1) h_aggr = segment_sum(h_dE[e]*sgn over f)
    fill_kernel<<<cdiv(F_NN * DD, 256), 256>>>(haggr, F_NN * DD, 0.f);
    scatter_aggr_kernel<<<cdiv(M_NN * 32, 256), 256>>>(h_dE, cob, haggr);

    // 2) h = h_aggr@aggr_W + aggr_b + h_dF@ctr_W + ctr_b
    {
        conv_act_kernel<<<cdiv(F_NN * 32, 256), 256>>>(haggr, F_NN, nullptr, 0, -1, apkH, apkL);
        GSegs s1 = {};
        s1.BH[0] = wpkH + o_aggr; s1.BL[0] = wpkL + o_aggr; s1.bias[0] = aggr_b;
        s1.C[0] = h0; s1.N[0] = 128; s1.acc[0] = 0; s1.start[0] = 0; s1.nseg = 1;
        gemm_multi<<<dim3(1, FY), 256, GEMM_SMEM>>>(apkH, apkL, F_NN, s1);

        conv_act_kernel<<<cdiv(F_NN * 32, 256), 256>>>(h_dF, F_NN, nullptr, 0, -1, apkH, apkL);
        GSegs s2 = {};
        s2.BH[0] = wpkH + o_ctr; s2.BL[0] = wpkL + o_ctr; s2.bias[0] = ctr_b;
        s2.C[0] = h0; s2.N[0] = 128; s2.acc[0] = 1; s2.start[0] = 0; s2.nseg = 1;
        gemm_multi<<<dim3(1, FY), 256, GEMM_SMEM>>>(apkH, apkL, F_NN, s2);
    }

    // 3) ea = h_dE[nn[:,2]] converted once (layer-invariant)
    conv_act_kernel<<<cdiv(P_NN * 32, 256), 256>>>(h_dE, P_NN, nn, 2, -1, eapkH, eapkL);

    float* hcur = h0;
    float* hnext = h1;
    for (int l = 0; l < 3; l++) {
        const float* bq = f_bq + (size_t)l * 384;
        const float* bk = f_bk + (size_t)l * 384;
        const float* bv = f_bv + (size_t)l * 384;
        const float* bs = f_bs + (size_t)l * 128;
        const int lo384 = l * 64 * 384;
        const int lo128 = l * 64 * 128;

        conv_act_kernel<<<cdiv(F_NN * 32, 256), 256>>>(hcur, F_NN, nullptr, 0, -1, apkH, apkL);

        // fused q,k,v,Ws GEMM over hcur
        GSegs sq = {};
        sq.BH[0] = wpkH + o_fq + lo384;  sq.BL[0] = wpkL + o_fq + lo384;
        sq.bias[0] = bq; sq.C[0] = q;     sq.N[0] = 384; sq.acc[0] = 0; sq.start[0] = 0;
        sq.BH[1] = wpkH + o_fk + lo384;  sq.BL[1] = wpkL + o_fk + lo384;
        sq.bias[1] = bk; sq.C[1] = k;     sq.N[1] = 384; sq.acc[1] = 0; sq.start[1] = 3;
        sq.BH[2] = wpkH + o_fv + lo384;  sq.BL[2] = wpkL + o_fv + lo384;
        sq.bias[2] = bv; sq.C[2] = v;     sq.N[2] = 384; sq.acc[2] = 0; sq.start[2] = 6;
        sq.BH[3] = wpkH + o_fws + lo128; sq.BL[3] = wpkL + o_fws + lo128;
        sq.bias[3] = bs; sq.C[3] = haggr; sq.N[3] = 128; sq.acc[3] = 0; sq.start[3] = 9;
        sq.nseg = 4;
        gemm_multi<<<dim3(10, FY), 256, GEMM_SMEM>>>(apkH, apkL, F_NN, sq);

        // ep = ea @ We
        GSegs se = {};
        se.BH[0] = wpkH + o_fwe + lo384; se.BL[0] = wpkL + o_fwe + lo384;
        se.bias[0] = nullptr; se.C[0] = ep; se.N[0] = 384; se.acc[0] = 0; se.start[0] = 0;
        se.nseg = 1;
        gemm_multi<<<dim3(3, PY), 256, GEMM_SMEM>>>(eapkH, eapkL, P_NN, se);

        fill_kernel<<<cdiv(F_NN * 3, 256), 256>>>(amax, F_NN * 3, 0.f);
        fill_kernel<<<cdiv(F_NN * 3, 256), 256>>>(den, F_NN * 3, 0.f);
        fill_kernel<<<cdiv(F_NN * HDD, 256), 256>>>(seg, F_NN * HDD, 0.f);

        attn_alpha_kernel<<<cdiv(P_NN, 8), 256>>>(q, k, ep, nn, 0, 1, P_NN, alpha, amax);
        attn_expden_kernel<<<cdiv(P_NN * 3, 256), 256>>>(nn, 1, P_NN, alpha, amax, den);
        attn_scatter_kernel<<<cdiv(P_NN, 8), 256>>>(v, ep, nn, 0, 1, P_NN, alpha, den, seg);

        combine_kernel<<<cdiv(F_NN * DD, 256), 256>>>(seg, hcur, haggr, hnext, F_NN);

        float* tmp = hcur; hcur = hnext; hnext = tmp;
    }

    // final cross attention: F -> E over cobdry edges (src=f_col(1), dst=e_col(0))
    {
        // q (E rows) + Ws (E rows) fused
        conv_act_kernel<<<cdiv(E_NN * 32, 256), 256>>>(h_dE, E_NN, nullptr, 0, -1, apkH, apkL);
        GSegs sq = {};
        sq.BH[0] = wpkH + o_eq;  sq.BL[0] = wpkL + o_eq;
        sq.bias[0] = e_bq; sq.C[0] = q;   sq.N[0] = 384; sq.acc[0] = 0; sq.start[0] = 0;
        sq.BH[1] = wpkH + o_ews; sq.BL[1] = wpkL + o_ews;
        sq.bias[1] = e_bs; sq.C[1] = wsE; sq.N[1] = 128; sq.acc[1] = 0; sq.start[1] = 3;
        sq.nseg = 2;
        gemm_multi<<<dim3(4, EY), 256, GEMM_SMEM>>>(apkH, apkL, E_NN, sq);

        // k + v (F rows) fused
        conv_act_kernel<<<cdiv(F_NN * 32, 256), 256>>>(hcur, F_NN, nullptr, 0, -1, apkH, apkL);
        GSegs skv = {};
        skv.BH[0] = wpkH + o_ek; skv.BL[0] = wpkL + o_ek;
        skv.bias[0] = e_bk; skv.C[0] = k; skv.N[0] = 384; skv.acc[0] = 0; skv.start[0] = 0;
        skv.BH[1] = wpkH + o_ev; skv.BL[1] = wpkL + o_ev;
        skv.bias[1] = e_bv; skv.C[1] = v; skv.N[1] = 384; skv.acc[1] = 0; skv.start[1] = 3;
        skv.nseg = 2;
        gemm_multi<<<dim3(6, FY), 256, GEMM_SMEM>>>(apkH, apkL, F_NN, skv);

        // ep = (hcur[cob[:,1]] * sgn) @ e_We  (gather+sign fused into convert)
        conv_act_kernel<<<cdiv(M_NN * 32, 256), 256>>>(hcur, M_NN, cob, 1, 2, apkH, apkL);
        GSegs se = {};
        se.BH[0] = wpkH + o_ewe; se.BL[0] = wpkL + o_ewe;
        se.bias[0] = nullptr; se.C[0] = ep; se.N[0] = 384; se.acc[0] = 0; se.start[0] = 0;
        se.nseg = 1;
        gemm_multi<<<dim3(3, MY), 256, GEMM_SMEM>>>(apkH, apkL, M_NN, se);
    }

    fill_kernel<<<cdiv(E_NN * 3, 256), 256>>>(amax, E_NN * 3, 0.f);
    fill_kernel<<<cdiv(E_NN * 3, 256), 256>>>(den, E_NN * 3, 0.f);
    fill_kernel<<<cdiv(E_NN * HDD, 256), 256>>>(seg, E_NN * HDD, 0.f);

    attn_alpha_kernel<<<cdiv(M_NN, 8), 256>>>(q, k, ep, cob, 1, 0, M_NN, alpha, amax);
    attn_expden_kernel<<<cdiv(M_NN * 3, 256), 256>>>(cob, 0, M_NN, alpha, amax, den);
    attn_scatter_kernel<<<cdiv(M_NN, 8), 256>>>(v, ep, cob, 1, 0, M_NN, alpha, den, seg);

    combine_kernel<<<cdiv(E_NN * DD, 256), 256>>>(seg, nullptr, wsE, out, E_NN);
}

// round 8
// speedup vs baseline: 1.7075x; 1.0686x over previous
#include <cuda_runtime.h>
#include <cuda_bf16.h>
#include <math.h>
#include <stdint.h>

#define E_NN 50000
#define F_NN 25000
#define M_NN 100000
#define P_NN 75000
#define DD   128
#define HDD  384

// ---------------- scratch (device globals; no allocation allowed) ----------------
__device__ float g_h0[F_NN * DD];
__device__ float g_h1[F_NN * DD];
__device__ float g_ws[F_NN * DD];      // Ws output (F layers)
__device__ float g_wsE[E_NN * DD];     // Ws output (E, final layer)
__device__ float g_q[E_NN * HDD];
__device__ float g_k[F_NN * HDD];
__device__ float g_v[F_NN * HDD];
__device__ float g_ep[M_NN * HDD];
// preconverted paired-bf16 operands
__device__ uint32_t g_apkH[64 * M_NN];
__device__ uint32_t g_apkL[64 * M_NN];
__device__ uint32_t g_eapkH[64 * P_NN];
__device__ uint32_t g_eapkL[64 * P_NN];
__device__ uint32_t g_wpkH[448 * 1024];
__device__ uint32_t g_wpkL[448 * 1024];
// CSR structures: [0]=nn by dst(col1), [1]=cob by f(col1), [2]=cob by e(col0)
__device__ int g_cnt[2 * F_NN + E_NN];
__device__ int g_cur[2 * F_NN + E_NN];
__device__ int g_off1[F_NN + 1];
__device__ int g_off2[F_NN + 1];
__device__ int g_off3[E_NN + 1];
__device__ int g_edg1[P_NN];
__device__ int g_edg2[M_NN];
__device__ int g_edg3[M_NN];

// ---------------- CSR build kernels ----------------
__global__ void fill_int_kernel(int* __restrict__ p, int n) {
    int t = blockIdx.x * blockDim.x + threadIdx.x;
    if (t < n) p[t] = 0;
}

__global__ void hist_kernel(const int* __restrict__ idx, int col, int n,
                            int* __restrict__ cnt) {
    int t = blockIdx.x * blockDim.x + threadIdx.x;
    if (t < n) atomicAdd(&cnt[idx[(size_t)t * 3 + col]], 1);
}

// one block per CSR: exclusive scan of cnt -> off, cur; off[n] = total
__global__ void scan3_kernel(const int* __restrict__ cntAll, int* __restrict__ curAll,
                             int* __restrict__ off1, int* __restrict__ off2,
                             int* __restrict__ off3) {
    __shared__ int sh[1024];
    __shared__ int carry;
    const int* cnt;
    int* cur;
    int* off;
    int n;
    if (blockIdx.x == 0) { cnt = cntAll; cur = curAll; off = off1; n = F_NN; }
    else if (blockIdx.x == 1) { cnt = cntAll + F_NN; cur = curAll + F_NN; off = off2; n = F_NN; }
    else { cnt = cntAll + 2 * F_NN; cur = curAll + 2 * F_NN; off = off3; n = E_NN; }
    int tid = threadIdx.x;
    if (tid == 0) carry = 0;
    __syncthreads();
    for (int base = 0; base < n; base += 1024) {
        int i = base + tid;
        int val = (i < n) ? cnt[i] : 0;
        sh[tid] = val;
        __syncthreads();
        for (int o = 1; o < 1024; o <<= 1) {
            int t = (tid >= o) ? sh[tid - o] : 0;
            __syncthreads();
            sh[tid] += t;
            __syncthreads();
        }
        int exc = sh[tid] - val;
        if (i < n) { off[i] = carry + exc; cur[i] = carry + exc; }
        __syncthreads();
        if (tid == 1023) carry += sh[1023];
        __syncthreads();
    }
    if (tid == 0) off[n] = carry;
}

__global__ void csr_scatter_kernel(const int* __restrict__ idx, int col, int n,
                                   int* __restrict__ cur, int* __restrict__ edg) {
    int t = blockIdx.x * blockDim.x + threadIdx.x;
    if (t >= n) return;
    int node = idx[(size_t)t * 3 + col];
    int pos = atomicAdd(&cur[node], 1);
    edg[pos] = t;
}

// ---------------- bf16 hi/lo packing helpers ----------------
__device__ __forceinline__ uint32_t bf2(float e0, float e1) {  // e0 -> low half
    __nv_bfloat162 t = __floats2bfloat162_rn(e0, e1);
    return *(uint32_t*)&t;
}
__device__ __forceinline__ float bfr(float x) {
    return __bfloat162float(__float2bfloat16_rn(x));
}

// activations: A[M][128] float (+optional gather/sign) -> Apk[m][64] u32 hi/lo
__global__ void conv_act_kernel(const float* __restrict__ A, int M,
                                const int* __restrict__ idx, int col, int sgnCol,
                                uint32_t* __restrict__ outH,
                                uint32_t* __restrict__ outL) {
    int t = blockIdx.x * blockDim.x + threadIdx.x;
    int r = t >> 5;
    if (r >= M) return;
    int lane = t & 31;
    int src = r;
    float sgn = 1.0f;
    if (idx) {
        src = idx[(size_t)r * 3 + col];
        if (sgnCol >= 0) sgn = (float)idx[(size_t)r * 3 + sgnCol];
    }
    float4 v = ((const float4*)(A + (size_t)src * 128))[lane];
    v.x *= sgn; v.y *= sgn; v.z *= sgn; v.w *= sgn;
    float h0 = bfr(v.x), h1 = bfr(v.y), h2 = bfr(v.z), h3 = bfr(v.w);
    size_t o = (size_t)r * 64 + lane * 2;
    outH[o + 0] = bf2(h0, h1);
    outH[o + 1] = bf2(h2, h3);
    outL[o + 0] = bf2(v.x - h0, v.y - h1);
    outL[o + 1] = bf2(v.z - h2, v.w - h3);
}

// all weights converted in one kernel
struct WSpec {
    const float* W[12];
    int start[12];   // u32 offset into wpk
    int N[12];
    int total;
};
__global__ void conv_w_all_kernel(WSpec ws,
                                  uint32_t* __restrict__ outH,
                                  uint32_t* __restrict__ outL) {
    int t = blockIdx.x * blockDim.x + threadIdx.x;
    if (t >= ws.total) return;
    int f = 0;
#pragma unroll
    for (int i = 1; i < 12; i++)
        if (t >= ws.start[i]) f = i;
    int rel = t - ws.start[f];
    int N = ws.N[f];
    int p2 = rel / N;          // (l*64 + pair)
    int n = rel - p2 * N;
    const float* src = ws.W[f] + (size_t)(2 * p2) * N + n;  // l*128 + 2*pair
    float v0 = src[0];
    float v1 = src[N];
    float h0 = bfr(v0), h1 = bfr(v1);
    outH[t] = bf2(h0, h1);
    outL[t] = bf2(v0 - h0, v1 - h1);
}

// initial aggregation: per f node, sum h_dE[ecol]*sgn over CSR(cob by f) -> packed apk
__global__ void aggr_conv_kernel(const int* __restrict__ off, const int* __restrict__ edg,
                                 const int* __restrict__ cob,
                                 const float* __restrict__ hE,
                                 uint32_t* __restrict__ outH,
                                 uint32_t* __restrict__ outL) {
    int f = blockIdx.x * 8 + (threadIdx.x >> 5);
    if (f >= F_NN) return;
    int lane = threadIdx.x & 31;
    float4 acc = make_float4(0.f, 0.f, 0.f, 0.f);
    int e1 = off[f + 1];
    for (int i = off[f]; i < e1; i++) {
        int eid = edg[i];
        int ecol = cob[(size_t)eid * 3 + 0];
        float sgn = (float)cob[(size_t)eid * 3 + 2];
        float4 x = ((const float4*)(hE + (size_t)ecol * DD))[lane];
        acc.x += sgn * x.x; acc.y += sgn * x.y;
        acc.z += sgn * x.z; acc.w += sgn * x.w;
    }
    float h0 = bfr(acc.x), h1 = bfr(acc.y), h2 = bfr(acc.z), h3 = bfr(acc.w);
    size_t o = (size_t)f * 64 + lane * 2;
    outH[o + 0] = bf2(h0, h1);
    outH[o + 1] = bf2(h2, h3);
    outL[o + 0] = bf2(acc.x - h0, acc.y - h1);
    outL[o + 1] = bf2(acc.z - h2, acc.w - h3);
}

// ---------------- BF16x3 tensor-core GEMM (preconverted, 3-stage pipeline) ----------------
__device__ __forceinline__ void mma_bf16(float* d,
                                         uint32_t a0, uint32_t a1, uint32_t a2, uint32_t a3,
                                         uint32_t b0, uint32_t b1) {
    asm volatile(
        "mma.sync.aligned.m16n8k16.row.col.f32.bf16.bf16.f32 "
        "{%0,%1,%2,%3}, {%4,%5,%6,%7}, {%8,%9}, {%0,%1,%2,%3};\n"
        : "+f"(d[0]), "+f"(d[1]), "+f"(d[2]), "+f"(d[3])
        : "r"(a0), "r"(a1), "r"(a2), "r"(a3), "r"(b0), "r"(b1));
}

__device__ __forceinline__ void cp16(void* smemDst, const void* gsrc) {
    uint32_t s = (uint32_t)__cvta_generic_to_shared(smemDst);
    asm volatile("cp.async.ca.shared.global [%0], [%1], 16;\n" :: "r"(s), "l"(gsrc));
}
#define CP_COMMIT() asm volatile("cp.async.commit_group;\n")
#define CP_WAIT(n)  asm volatile("cp.async.wait_group %0;\n" :: "n"(n))

#define BM 128
#define BN 128
#define STAGES 3
#define ASTRIDE 12
#define BSTRIDE 136
#define A_ST_U32 (128 * ASTRIDE)
#define B_ST_U32 (8 * BSTRIDE)
#define GEMM_SMEM (STAGES * (2 * A_ST_U32 + 2 * B_ST_U32) * 4)  // 62976

struct GSegs {
    const uint32_t* BH[4];
    const uint32_t* BL[4];
    const float* bias[4];
    float* C[4];
    uint32_t* eH[4];   // optional packed output (N must be 128)
    uint32_t* eL[4];
    int N[4];
    int acc[4];
    int start[4];
    int nseg;
};

__global__ __launch_bounds__(256, 2) void gemm_multi(
    const uint32_t* __restrict__ apkH, const uint32_t* __restrict__ apkL,
    int M, GSegs segs)
{
    extern __shared__ uint32_t smu[];
    uint32_t* AsH = smu;
    uint32_t* AsL = smu + STAGES * A_ST_U32;
    uint32_t* BsH = smu + 2 * STAGES * A_ST_U32;
    uint32_t* BsL = BsH + STAGES * B_ST_U32;

    const int tid = threadIdx.x;
    const int lane = tid & 31;
    const int warp = tid >> 5;
    const int warp_m = warp & 1;
    const int warp_n = warp >> 1;
    const int row0 = blockIdx.y * BM;

    int s = 0;
#pragma unroll
    for (int t = 1; t < 4; t++)
        if (t < segs.nseg && (int)blockIdx.x >= segs.start[t]) s = t;
    const uint32_t* BHp = segs.BH[s];
    const uint32_t* BLp = segs.BL[s];
    const float* bias = segs.bias[s];
    float* C = segs.C[s];
    uint32_t* eH = segs.eH[s];
    uint32_t* eL = segs.eL[s];
    const int N = segs.N[s];
    const int accum = segs.acc[s];
    const int col0 = (blockIdx.x - segs.start[s]) * BN;

    const int grp = lane >> 2;
    const int qid = lane & 3;

    const int a_m = tid >> 1;
    const int a_c = tid & 1;
    const int b_kp = tid >> 5;
    const int b_ch = tid & 31;

    const int arow = (row0 + a_m < M) ? (row0 + a_m) : (M - 1);
    const uint32_t* gAH = apkH + (size_t)arow * 64 + a_c * 4;
    const uint32_t* gAL = apkL + (size_t)arow * 64 + a_c * 4;
    const uint32_t* gBH = BHp + (size_t)b_kp * N + col0 + b_ch * 4;
    const uint32_t* gBL = BLp + (size_t)b_kp * N + col0 + b_ch * 4;

    float acc[4][4][4];
#pragma unroll
    for (int i = 0; i < 4; i++)
#pragma unroll
        for (int j = 0; j < 4; j++)
#pragma unroll
            for (int r = 0; r < 4; r++) acc[i][j][r] = 0.f;

    auto stage = [&](int slot, int kp0) {
        uint32_t* aH = AsH + slot * A_ST_U32 + a_m * ASTRIDE + a_c * 4;
        uint32_t* aL = AsL + slot * A_ST_U32 + a_m * ASTRIDE + a_c * 4;
        cp16(aH, gAH + kp0);
        cp16(aL, gAL + kp0);
        uint32_t* bH = BsH + slot * B_ST_U32 + b_kp * BSTRIDE + b_ch * 4;
        uint32_t* bL = BsL + slot * B_ST_U32 + b_kp * BSTRIDE + b_ch * 4;
        cp16(bH, gBH + (size_t)kp0 * N);
        cp16(bL, gBL + (size_t)kp0 * N);
    };

    stage(0, 0);
    CP_COMMIT();
    stage(1, 8);
    CP_COMMIT();

    for (int it = 0; it < 8; it++) {
        CP_WAIT(1);
        __syncthreads();
        const int buf = it % STAGES;
        const uint32_t* cAH = AsH + buf * A_ST_U32;
        const uint32_t* cAL = AsL + buf * A_ST_U32;
        const uint32_t* cBH = BsH + buf * B_ST_U32;
        const uint32_t* cBL = BsL + buf * B_ST_U32;

        uint32_t afH[4][4], afL[4][4];
        uint32_t bfH[4][2], bfL[4][2];
#pragma unroll
        for (int i = 0; i < 4; i++) {
            int mr = warp_m * 64 + i * 16 + grp;
            afH[i][0] = cAH[mr * ASTRIDE + qid];
            afH[i][1] = cAH[(mr + 8) * ASTRIDE + qid];
            afH[i][2] = cAH[mr * ASTRIDE + qid + 4];
            afH[i][3] = cAH[(mr + 8) * ASTRIDE + qid + 4];
            afL[i][0] = cAL[mr * ASTRIDE + qid];
            afL[i][1] = cAL[(mr + 8) * ASTRIDE + qid];
            afL[i][2] = cAL[mr * ASTRIDE + qid + 4];
            afL[i][3] = cAL[(mr + 8) * ASTRIDE + qid + 4];
        }
#pragma unroll
        for (int j = 0; j < 4; j++) {
            int nb = warp_n * 32 + j * 8 + grp;
            bfH[j][0] = cBH[qid * BSTRIDE + nb];
            bfH[j][1] = cBH[(qid + 4) * BSTRIDE + nb];
            bfL[j][0] = cBL[qid * BSTRIDE + nb];
            bfL[j][1] = cBL[(qid + 4) * BSTRIDE + nb];
        }
#pragma unroll
        for (int i = 0; i < 4; i++)
#pragma unroll
            for (int j = 0; j < 4; j++) {
                mma_bf16(acc[i][j], afH[i][0], afH[i][1], afH[i][2], afH[i][3],
                         bfH[j][0], bfH[j][1]);
                mma_bf16(acc[i][j], afH[i][0], afH[i][1], afH[i][2], afH[i][3],
                         bfL[j][0], bfL[j][1]);
                mma_bf16(acc[i][j], afL[i][0], afL[i][1], afL[i][2], afL[i][3],
                         bfH[j][0], bfH[j][1]);
            }

        int nxt = it + STAGES - 1;
        if (nxt < 8) stage(nxt % STAGES, nxt * 8);
        CP_COMMIT();
    }

#pragma unroll
    for (int i = 0; i < 4; i++) {
        int row = row0 + warp_m * 64 + i * 16 + grp;
#pragma unroll
        for (int j = 0; j < 4; j++) {
            int col = col0 + warp_n * 32 + j * 8 + qid * 2;
#pragma unroll
            for (int half = 0; half < 2; half++) {
                int r = row + half * 8;
                if (r >= M) continue;
                float2 res;
                res.x = acc[i][j][half * 2 + 0];
                res.y = acc[i][j][half * 2 + 1];
                if (bias) {
                    res.x += bias[col + 0];
                    res.y += bias[col + 1];
                }
                float2* cp = (float2*)(C + (size_t)r * N + col);
                if (accum) {
                    float2 old = *cp;
                    res.x += old.x;
                    res.y += old.y;
                }
                *cp = res;
                if (eH) {
                    float hx = bfr(res.x), hy = bfr(res.y);
                    size_t o = (size_t)r * 64 + (col >> 1);
                    eH[o] = bf2(hx, hy);
                    eL[o] = bf2(res.x - hx, res.y - hy);
                }
            }
        }
    }
}

// ---------------- fused CSR attention (online softmax, warp per dst node) ----------------
__global__ void attn_csr_kernel(
    const int* __restrict__ off, const int* __restrict__ edg,
    const int* __restrict__ idx, int srcCol,
    const float* __restrict__ q, const float* __restrict__ k,
    const float* __restrict__ v, const float* __restrict__ ep,
    const float* __restrict__ hin, const float* __restrict__ ws,
    float* __restrict__ outp,
    uint32_t* __restrict__ apkH, uint32_t* __restrict__ apkL,
    int Nn)
{
    int node = blockIdx.x * 8 + (threadIdx.x >> 5);
    if (node >= Nn) return;
    int lane = threadIdx.x & 31;
    const float4* qp = (const float4*)(q + (size_t)node * HDD);
    float4 qv[3];
    qv[0] = qp[lane]; qv[1] = qp[32 + lane]; qv[2] = qp[64 + lane];
    float m[3] = {-INFINITY, -INFINITY, -INFINITY};
    float dd[3] = {0.f, 0.f, 0.f};
    float4 aa[3];
    aa[0] = aa[1] = aa[2] = make_float4(0.f, 0.f, 0.f, 0.f);

    int iend = off[node + 1];
    for (int i = off[node]; i < iend; i++) {
        int eid = edg[i];
        int src = idx[(size_t)eid * 3 + srcCol];
        const float4* kp = (const float4*)(k + (size_t)src * HDD);
        const float4* vp = (const float4*)(v + (size_t)src * HDD);
        const float4* epp = (const float4*)(ep + (size_t)eid * HDD);
#pragma unroll
        for (int h = 0; h < 3; h++) {
            float4 kv = kp[h * 32 + lane];
            float4 ev = epp[h * 32 + lane];
            float4 vv = vp[h * 32 + lane];
            float sc = qv[h].x * (kv.x + ev.x) + qv[h].y * (kv.y + ev.y) +
                       qv[h].z * (kv.z + ev.z) + qv[h].w * (kv.w + ev.w);
#pragma unroll
            for (int o = 16; o > 0; o >>= 1) sc += __shfl_xor_sync(0xffffffffu, sc, o);
            sc *= 0.08838834764831845f;  // 1/sqrt(128)
            float nm = fmaxf(m[h], sc);
            float sl = __expf(m[h] - nm);
            float p = __expf(sc - nm);
            dd[h] = dd[h] * sl + p;
            aa[h].x = aa[h].x * sl + p * (vv.x + ev.x);
            aa[h].y = aa[h].y * sl + p * (vv.y + ev.y);
            aa[h].z = aa[h].z * sl + p * (vv.z + ev.z);
            aa[h].w = aa[h].w * sl + p * (vv.w + ev.w);
            m[h] = nm;
        }
    }

    float4 o4 = make_float4(0.f, 0.f, 0.f, 0.f);
#pragma unroll
    for (int h = 0; h < 3; h++) {
        float inv = (dd[h] > 0.f) ? 1.f / (dd[h] + 1e-16f) : 0.f;
        o4.x += aa[h].x * inv;
        o4.y += aa[h].y * inv;
        o4.z += aa[h].z * inv;
        o4.w += aa[h].w * inv;
    }
    const float third = 1.0f / 3.0f;
    o4.x *= third; o4.y *= third; o4.z *= third; o4.w *= third;
    if (hin) {
        float4 t = ((const float4*)(hin + (size_t)node * DD))[lane];
        o4.x += t.x; o4.y += t.y; o4.z += t.z; o4.w += t.w;
    }
    if (ws) {
        float4 t = ((const float4*)(ws + (size_t)node * DD))[lane];
        o4.x += t.x; o4.y += t.y; o4.z += t.z; o4.w += t.w;
    }
    ((float4*)(outp + (size_t)node * DD))[lane] = o4;
    if (apkH) {
        float h0 = bfr(o4.x), h1 = bfr(o4.y), h2 = bfr(o4.z), h3 = bfr(o4.w);
        size_t o = (size_t)node * 64 + lane * 2;
        apkH[o + 0] = bf2(h0, h1);
        apkH[o + 1] = bf2(h2, h3);
        apkL[o + 0] = bf2(o4.x - h0, o4.y - h1);
        apkL[o + 1] = bf2(o4.z - h2, o4.w - h3);
    }
}

// ---------------- host orchestration ----------------
static inline int cdiv(int a, int b) { return (a + b - 1) / b; }

extern "C" void kernel_launch(void* const* d_in, const int* in_sizes, int n_in,
                              void* d_out, int out_size) {
    const float* h_dE = (const float*)d_in[0];
    const float* h_dF = (const float*)d_in[1];
    const int* cob = (const int*)d_in[2];
    const int* nn = (const int*)d_in[3];
    const float* aggr_W = (const float*)d_in[4];
    const float* aggr_b = (const float*)d_in[5];
    const float* ctr_W = (const float*)d_in[6];
    const float* ctr_b = (const float*)d_in[7];
    const float* f_Wq = (const float*)d_in[8];
    const float* f_bq = (const float*)d_in[9];
    const float* f_Wk = (const float*)d_in[10];
    const float* f_bk = (const float*)d_in[11];
    const float* f_Wv = (const float*)d_in[12];
    const float* f_bv = (const float*)d_in[13];
    const float* f_We = (const float*)d_in[14];
    const float* f_Ws = (const float*)d_in[15];
    const float* f_bs = (const float*)d_in[16];
    const float* e_Wq = (const float*)d_in[17];
    const float* e_bq = (const float*)d_in[18];
    const float* e_Wk = (const float*)d_in[19];
    const float* e_bk = (const float*)d_in[20];
    const float* e_Wv = (const float*)d_in[21];
    const float* e_bv = (const float*)d_in[22];
    const float* e_We = (const float*)d_in[23];
    const float* e_Ws = (const float*)d_in[24];
    const float* e_bs = (const float*)d_in[25];
    float* out = (float*)d_out;

    cudaFuncSetAttribute(gemm_multi, cudaFuncAttributeMaxDynamicSharedMemorySize, GEMM_SMEM);

    float *h0, *h1, *wsF, *wsE, *q, *k, *v, *ep;
    uint32_t *apkH, *apkL, *eapkH, *eapkL, *wpkH, *wpkL;
    int *cnt, *cur, *off1, *off2, *off3, *edg1, *edg2, *edg3;
    cudaGetSymbolAddress((void**)&h0, g_h0);
    cudaGetSymbolAddress((void**)&h1, g_h1);
    cudaGetSymbolAddress((void**)&wsF, g_ws);
    cudaGetSymbolAddress((void**)&wsE, g_wsE);
    cudaGetSymbolAddress((void**)&q, g_q);
    cudaGetSymbolAddress((void**)&k, g_k);
    cudaGetSymbolAddress((void**)&v, g_v);
    cudaGetSymbolAddress((void**)&ep, g_ep);
    cudaGetSymbolAddress((void**)&apkH, g_apkH);
    cudaGetSymbolAddress((void**)&apkL, g_apkL);
    cudaGetSymbolAddress((void**)&eapkH, g_eapkH);
    cudaGetSymbolAddress((void**)&eapkL, g_eapkL);
    cudaGetSymbolAddress((void**)&wpkH, g_wpkH);
    cudaGetSymbolAddress((void**)&wpkL, g_wpkL);
    cudaGetSymbolAddress((void**)&cnt, g_cnt);
    cudaGetSymbolAddress((void**)&cur, g_cur);
    cudaGetSymbolAddress((void**)&off1, g_off1);
    cudaGetSymbolAddress((void**)&off2, g_off2);
    cudaGetSymbolAddress((void**)&off3, g_off3);
    cudaGetSymbolAddress((void**)&edg1, g_edg1);
    cudaGetSymbolAddress((void**)&edg2, g_edg2);
    cudaGetSymbolAddress((void**)&edg3, g_edg3);

    const int FY = cdiv(F_NN, 128);
    const int EY = cdiv(E_NN, 128);
    const int PY = cdiv(P_NN, 128);
    const int MY = cdiv(M_NN, 128);

    // ---- CSR build ----
    const int NCNT = 2 * F_NN + E_NN;
    fill_int_kernel<<<cdiv(NCNT, 256), 256>>>(cnt, NCNT);
    hist_kernel<<<cdiv(P_NN, 256), 256>>>(nn, 1, P_NN, cnt);
    hist_kernel<<<cdiv(M_NN, 256), 256>>>(cob, 1, M_NN, cnt + F_NN);
    hist_kernel<<<cdiv(M_NN, 256), 256>>>(cob, 0, M_NN, cnt + 2 * F_NN);
    scan3_kernel<<<3, 1024>>>(cnt, cur, off1, off2, off3);
    csr_scatter_kernel<<<cdiv(P_NN, 256), 256>>>(nn, 1, P_NN, cur, edg1);
    csr_scatter_kernel<<<cdiv(M_NN, 256), 256>>>(cob, 1, M_NN, cur + F_NN, edg2);
    csr_scatter_kernel<<<cdiv(M_NN, 256), 256>>>(cob, 0, M_NN, cur + 2 * F_NN, edg3);

    // ---- weight conversion (single kernel) ----
    WSpec wsp;
    {
        const float* Ws[12] = {aggr_W, ctr_W, f_Wq, f_Wk, f_Wv, f_We, f_Ws,
                               e_Wq, e_Wk, e_Wv, e_We, e_Ws};
        int Ns[12] = {128, 128, 384, 384, 384, 384, 128, 384, 384, 384, 384, 128};
        int Ls[12] = {1, 1, 3, 3, 3, 3, 3, 1, 1, 1, 1, 1};
        int o = 0;
        for (int i = 0; i < 12; i++) {
            wsp.W[i] = Ws[i];
            wsp.start[i] = o;
            wsp.N[i] = Ns[i];
            o += 64 * Ns[i] * Ls[i];
        }
        wsp.total = o;
    }
    conv_w_all_kernel<<<cdiv(wsp.total, 256), 256>>>(wsp, wpkH, wpkL);
    const int o_aggr = wsp.start[0], o_ctr = wsp.start[1];
    const int o_fq = wsp.start[2], o_fk = wsp.start[3], o_fv = wsp.start[4];
    const int o_fwe = wsp.start[5], o_fws = wsp.start[6];
    const int o_eq = wsp.start[7], o_ek = wsp.start[8], o_ev = wsp.start[9];
    const int o_ewe = wsp.start[10], o_ews = wsp.start[11];

    // ---- init: h0 = aggr@aggr_W + aggr_b + h_dF@ctr_W + ctr_b ----
    aggr_conv_kernel<<<cdiv(F_NN, 8), 256>>>(off2, edg2, cob, h_dE, apkH, apkL);
    {
        GSegs s1 = {};
        s1.BH[0] = wpkH + o_aggr; s1.BL[0] = wpkL + o_aggr; s1.bias[0] = aggr_b;
        s1.C[0] = h0; s1.N[0] = 128; s1.acc[0] = 0; s1.start[0] = 0; s1.nseg = 1;
        gemm_multi<<<dim3(1, FY), 256, GEMM_SMEM>>>(apkH, apkL, F_NN, s1);
    }
    conv_act_kernel<<<cdiv(F_NN * 32, 256), 256>>>(h_dF, F_NN, nullptr, 0, -1, apkH, apkL);
    {
        GSegs s2 = {};
        s2.BH[0] = wpkH + o_ctr; s2.BL[0] = wpkL + o_ctr; s2.bias[0] = ctr_b;
        s2.C[0] = h0; s2.N[0] = 128; s2.acc[0] = 1; s2.start[0] = 0;
        s2.eH[0] = apkH; s2.eL[0] = apkL;   // emit packed h0 for layer-1 GEMM
        s2.nseg = 1;
        gemm_multi<<<dim3(1, FY), 256, GEMM_SMEM>>>(apkH, apkL, F_NN, s2);
    }

    // ea = h_dE[nn[:,2]] packed once (layer-invariant)
    conv_act_kernel<<<cdiv(P_NN * 32, 256), 256>>>(h_dE, P_NN, nn, 2, -1, eapkH, eapkL);

    float* hcur = h0;
    float* hnext = h1;
    for (int l = 0; l < 3; l++) {
        const float* bq = f_bq + (size_t)l * 384;
        const float* bk = f_bk + (size_t)l * 384;
        const float* bv = f_bv + (size_t)l * 384;
        const float* bs = f_bs + (size_t)l * 128;
        const int lo384 = l * 64 * 384;
        const int lo128 = l * 64 * 128;

        GSegs sq = {};
        sq.BH[0] = wpkH + o_fq + lo384;  sq.BL[0] = wpkL + o_fq + lo384;
        sq.bias[0] = bq; sq.C[0] = q;   sq.N[0] = 384; sq.acc[0] = 0; sq.start[0] = 0;
        sq.BH[1] = wpkH + o_fk + lo384;  sq.BL[1] = wpkL + o_fk + lo384;
        sq.bias[1] = bk; sq.C[1] = k;   sq.N[1] = 384; sq.acc[1] = 0; sq.start[1] = 3;
        sq.BH[2] = wpkH + o_fv + lo384;  sq.BL[2] = wpkL + o_fv + lo384;
        sq.bias[2] = bv; sq.C[2] = v;   sq.N[2] = 384; sq.acc[2] = 0; sq.start[2] = 6;
        sq.BH[3] = wpkH + o_fws + lo128; sq.BL[3] = wpkL + o_fws + lo128;
        sq.bias[3] = bs; sq.C[3] = wsF; sq.N[3] = 128; sq.acc[3] = 0; sq.start[3] = 9;
        sq.nseg = 4;
        gemm_multi<<<dim3(10, FY), 256, GEMM_SMEM>>>(apkH, apkL, F_NN, sq);

        GSegs se = {};
        se.BH[0] = wpkH + o_fwe + lo384; se.BL[0] = wpkL + o_fwe + lo384;
        se.bias[0] = nullptr; se.C[0] = ep; se.N[0] = 384; se.acc[0] = 0; se.start[0] = 0;
        se.nseg = 1;
        gemm_multi<<<dim3(3, PY), 256, GEMM_SMEM>>>(eapkH, eapkL, P_NN, se);

        // fused attention + residual + Ws + next-layer packing
        attn_csr_kernel<<<cdiv(F_NN, 8), 256>>>(off1, edg1, nn, 0,
                                                q, k, v, ep, hcur, wsF,
                                                hnext, apkH, apkL, F_NN);

        float* tmp = hcur; hcur = hnext; hnext = tmp;
    }

    // ---- final cross attention: F -> E over cobdry edges ----
    {
        // q (E rows) + wsE, A = packed h_dE
        conv_act_kernel<<<cdiv(E_NN * 32, 256), 256>>>(h_dE, E_NN, nullptr, 0, -1, eapkH, eapkL);
        GSegs sq = {};
        sq.BH[0] = wpkH + o_eq;  sq.BL[0] = wpkL + o_eq;
        sq.bias[0] = e_bq; sq.C[0] = q;   sq.N[0] = 384; sq.acc[0] = 0; sq.start[0] = 0;
        sq.BH[1] = wpkH + o_ews; sq.BL[1] = wpkL + o_ews;
        sq.bias[1] = e_bs; sq.C[1] = wsE; sq.N[1] = 128; sq.acc[1] = 0; sq.start[1] = 3;
        sq.nseg = 2;
        gemm_multi<<<dim3(4, EY), 256, GEMM_SMEM>>>(eapkH, eapkL, E_NN, sq);

        // k + v from packed hcur (emitted by layer-3 attention)
        GSegs skv = {};
        skv.BH[0] = wpkH + o_ek; skv.BL[0] = wpkL + o_ek;
        skv.bias[0] = e_bk; skv.C[0] = k; skv.N[0] = 384; skv.acc[0] = 0; skv.start[0] = 0;
        skv.BH[1] = wpkH + o_ev; skv.BL[1] = wpkL + o_ev;
        skv.bias[1] = e_bv; skv.C[1] = v; skv.N[1] = 384; skv.acc[1] = 0; skv.start[1] = 3;
        skv.nseg = 2;
        gemm_multi<<<dim3(6, FY), 256, GEMM_SMEM>>>(apkH, apkL, F_NN, skv);

        // ep = (hcur[cob[:,1]] * sgn) @ e_We
        conv_act_kernel<<<cdiv(M_NN * 32, 256), 256>>>(hcur, M_NN, cob, 1, 2, apkH, apkL);
        GSegs se = {};
        se.BH[0] = wpkH + o_ewe; se.BL[0] = wpkL + o_ewe;
        se.bias[0] = nullptr; se.C[0] = ep; se.N[0] = 384; se.acc[0] = 0; se.start[0] = 0;
        se.nseg = 1;
        gemm_multi<<<dim3(3, MY), 256, GEMM_SMEM>>>(apkH, apkL, M_NN, se);

        // final attention: dst = e_col (CSR3), src = f_col (col 1); out = mean + wsE
        attn_csr_kernel<<<cdiv(E_NN, 8), 256>>>(off3, edg3, cob, 1,
                                                q, k, v, ep, nullptr, wsE,
                                                out, nullptr, nullptr, E_NN);
    }
}